// round 2
// baseline (speedup 1.0000x reference)
#include <cuda_runtime.h>
#include <math.h>

#define BB 8
#define CC 128
#define NN 9216
#define EE 16

// ---------------- scratch (device globals; no allocation) ----------------
__device__ float g_node [BB*NN*CC];
__device__ float g_intra[BB*NN*CC];
__device__ float g_cross[BB*NN*CC];
__device__ float g_gate [BB*NN*CC];
__device__ float g_part [BB*36*EE*CC];
__device__ float g_hyper [BB*EE*CC];
__device__ float g_hyperF[BB*EE*CC];
__device__ float g_K[BB*EE*CC];
__device__ float g_V[BB*EE*CC];

__device__ __forceinline__ float gelu_exact(float x){
    return 0.5f*x*(1.0f + erff(x*0.70710678118654752f));
}

// ---------------- kernel 1: transpose + LayerNorm(node) ----------------
// grid 2304 (= 8 * 288), block 128, 32 nodes per block
__global__ void k_node_ln(const float* __restrict__ fm,
                          const float* __restrict__ gam,
                          const float* __restrict__ bet)
{
    __shared__ float tile[32*132];
    __shared__ float s_mean[32], s_rstd[32];
    int b  = blockIdx.x / 288;
    int n0 = (blockIdx.x % 288) * 32;
    int tid = threadIdx.x;
    for (int i = tid; i < 4096; i += 128){
        int c = i >> 5, n = i & 31;
        tile[n*132 + c] = fm[(b*CC + c)*NN + n0 + n];
    }
    __syncthreads();
    int w = tid >> 5, lane = tid & 31;
    for (int n = w*8; n < w*8 + 8; n++){
        float v0 = tile[n*132+lane],    v1 = tile[n*132+lane+32];
        float v2 = tile[n*132+lane+64], v3 = tile[n*132+lane+96];
        float s = v0+v1+v2+v3;
        for (int o=16;o;o>>=1) s += __shfl_xor_sync(0xffffffffu, s, o);
        float m = s * (1.0f/128.0f);
        float d0=v0-m, d1=v1-m, d2=v2-m, d3=v3-m;
        float q = d0*d0+d1*d1+d2*d2+d3*d3;
        for (int o=16;o;o>>=1) q += __shfl_xor_sync(0xffffffffu, q, o);
        if (lane == 0){ s_mean[n]=m; s_rstd[n]=rsqrtf(q*(1.0f/128.0f)+1e-5f); }
    }
    __syncthreads();
    float gg = gam[tid], bb = bet[tid];
    for (int n = 0; n < 32; n++){
        float v = (tile[n*132+tid]-s_mean[n])*s_rstd[n]*gg + bb;
        g_node[(b*NN + n0 + n)*CC + tid] = v;
    }
}

// ---------------- kernel 2: hyperedge aggregation partials ----------------
// grid 288 (= 8 * 36), block 128, 256 nodes per block
__global__ void k_agg(const float* __restrict__ sc)
{
    __shared__ float s_sc[256*16];
    int b  = blockIdx.x / 36;
    int ch = blockIdx.x % 36;
    int n0 = ch*256;
    int tid = threadIdx.x;
    for (int i = tid; i < 4096; i += 128)
        s_sc[i] = sc[(b*NN + n0)*EE + i];
    __syncthreads();
    float acc[16];
    #pragma unroll
    for (int e=0;e<16;e++) acc[e]=0.f;
    for (int n = 0; n < 256; n++){
        float x = g_node[(b*NN + n0 + n)*CC + tid];
        #pragma unroll
        for (int e=0;e<16;e++) acc[e] += s_sc[n*16+e]*x;
    }
    #pragma unroll
    for (int e=0;e<16;e++)
        g_part[((b*36 + ch)*EE + e)*CC + tid] = acc[e];
}

// ---------------- kernel 3: reduce partials ----------------
__global__ void k_reduce()
{
    int i = blockIdx.x*1024 + threadIdx.x;   // 16384 total
    int b = i >> 11, rem = i & 2047;
    float s = 0.f;
    for (int j = 0; j < 36; j++) s += g_part[(b*36 + j)*2048 + rem];
    g_hyper[b*2048 + rem] = s;
}

// ---------------- kernel 4: hyperedge transformer pipeline ----------------
// grid 8, block 512
__device__ __forceinline__ void gemm16(const float* __restrict__ W,
                                       const float* __restrict__ bias,
                                       const float* in, int inPitch, int Cin,
                                       float* out, int outPitch,
                                       float* sw, int Cout, int act)
{
    for (int j0 = 0; j0 < Cout; j0 += 32){
        __syncthreads();
        for (int i = threadIdx.x; i < 32*Cin; i += 512){
            int r = i / Cin, cc = i - r*Cin;
            sw[r*264 + cc] = W[(j0+r)*Cin + cc];
        }
        __syncthreads();
        int p = threadIdx.x;
        int e = p & 15, jj = p >> 4;
        const float4* a  = (const float4*)(in + e*inPitch);
        const float4* w4 = (const float4*)(sw + jj*264);
        float acc = 0.f;
        int K4 = Cin >> 2;
        for (int kk = 0; kk < K4; kk++){
            float4 av = a[kk], wv = w4[kk];
            acc += av.x*wv.x + av.y*wv.y + av.z*wv.z + av.w*wv.w;
        }
        acc += bias[j0+jj];
        if (act) acc = gelu_exact(acc);
        out[e*outPitch + j0 + jj] = acc;
    }
    __syncthreads();
}

__device__ __forceinline__ void ln16_128(const float* a, const float* r, int pitch,
                                         const float* __restrict__ g,
                                         const float* __restrict__ b,
                                         float* out, int outPitch)
{
    int w = threadIdx.x >> 5, lane = threadIdx.x & 31;
    if (w < 16){
        float v[4]; float s = 0.f;
        #pragma unroll
        for (int i=0;i<4;i++){
            float x = a[w*pitch + lane + 32*i];
            if (r) x += r[w*pitch + lane + 32*i];
            v[i] = x; s += x;
        }
        for (int o=16;o;o>>=1) s += __shfl_xor_sync(0xffffffffu, s, o);
        float m = s*(1.f/128.f), q = 0.f;
        #pragma unroll
        for (int i=0;i<4;i++){ float d=v[i]-m; q += d*d; }
        for (int o=16;o;o>>=1) q += __shfl_xor_sync(0xffffffffu, q, o);
        float rs = rsqrtf(q*(1.f/128.f)+1e-5f);
        #pragma unroll
        for (int i=0;i<4;i++)
            out[w*outPitch + lane + 32*i] = (v[i]-m)*rs*g[lane+32*i] + b[lane+32*i];
    }
    __syncthreads();
}

__global__ void k_hyper(const float* __restrict__ mha_w_in, const float* __restrict__ mha_b_in,
                        const float* __restrict__ mha_w_out, const float* __restrict__ mha_b_out,
                        const float* __restrict__ ffn_w1, const float* __restrict__ ffn_b1,
                        const float* __restrict__ ffn_w2, const float* __restrict__ ffn_b2,
                        const float* __restrict__ tnorm_g, const float* __restrict__ tnorm_b,
                        const float* __restrict__ nh_g, const float* __restrict__ nh_b,
                        const float* __restrict__ hp_w, const float* __restrict__ hp_b,
                        const float* __restrict__ kv_w, const float* __restrict__ kv_b)
{
    extern __shared__ float sm[];
    float* s0   = sm;            // 16*132 hyper (kept for residual)
    float* s1   = s0 + 2112;     // q -> ao -> ffn_out -> K
    float* s2   = s1 + 2112;     // k -> attn proj -> hyper2 -> V
    float* s3   = s2 + 2112;     // v -> x(post LN1) -> hyper3
    float* sh   = s3 + 2112;     // 16*264 ffn hidden
    float* sw   = sh + 4224;     // 32*264 weight staging
    float* satt = sw + 8448;     // 4*16*16
    int b = blockIdx.x, tid = threadIdx.x;

    for (int i = tid; i < 2048; i += 512)
        s0[(i>>7)*132 + (i&127)] = g_hyper[b*2048 + i];
    __syncthreads();

    gemm16(mha_w_in,           mha_b_in,     s0,132,128, s1,132, sw,128,0);  // q
    gemm16(mha_w_in + 128*128, mha_b_in+128, s0,132,128, s2,132, sw,128,0);  // k
    gemm16(mha_w_in + 256*128, mha_b_in+256, s0,132,128, s3,132, sw,128,0);  // v

    for (int p = tid; p < 1024; p += 512){
        int h = p>>8, e1 = (p>>4)&15, e2 = p&15;
        const float* qr = s1 + e1*132 + h*32;
        const float* kr = s2 + e2*132 + h*32;
        float acc = 0.f;
        #pragma unroll
        for (int d=0; d<32; d++) acc += qr[d]*kr[d];
        satt[p] = acc * 0.17677669529663687f;   // 1/sqrt(32)
    }
    __syncthreads();
    if (tid < 64){
        float* row = satt + tid*16;
        float mx = row[0];
        #pragma unroll
        for (int e=1;e<16;e++) mx = fmaxf(mx, row[e]);
        float s = 0.f;
        #pragma unroll
        for (int e=0;e<16;e++){ float v = expf(row[e]-mx); row[e]=v; s+=v; }
        float inv = 1.f/s;
        #pragma unroll
        for (int e=0;e<16;e++) row[e] *= inv;
    }
    __syncthreads();
    for (int p = tid; p < 2048; p += 512){  // ao -> s1 (q dead)
        int e = p>>7, c = p&127, h = c>>5;
        float acc = 0.f;
        #pragma unroll
        for (int e2=0;e2<16;e2++) acc += satt[(h*16+e)*16 + e2] * s3[e2*132 + c];
        s1[e*132 + c] = acc;
    }
    gemm16(mha_w_out, mha_b_out, s1,132,128, s2,132, sw,128,0);   // attn out proj
    ln16_128(s0, s2, 132, tnorm_g, tnorm_b, s3, 132);             // x = LN(hyper+ao)
    gemm16(ffn_w1, ffn_b1, s3,132,128, sh,264, sw,256,1);         // hidden (gelu)
    gemm16(ffn_w2, ffn_b2, sh,264,256, s1,132, sw,128,0);         // ffn out
    ln16_128(s3, s1, 132, tnorm_g, tnorm_b, s2, 132);             // hyper2
    ln16_128(s2, (const float*)0, 132, nh_g, nh_b, s3, 132);      // hyper3 = LN(nh)
    gemm16(hp_w, hp_b, s3,132,128, s0,132, sw,128,1);             // hyperF = gelu(hp)
    gemm16(kv_w,           kv_b,     s0,132,128, s1,132, sw,128,0);  // K
    gemm16(kv_w + 128*128, kv_b+128, s0,132,128, s2,132, sw,128,0);  // V

    for (int i = tid; i < 2048; i += 512){
        int e = i>>7, c = i&127, o = b*2048 + i;
        g_hyperF[o] = s0[e*132+c];
        g_K[o]      = s1[e*132+c];
        g_V[o]      = s2[e*132+c];
    }
}

// ---------------- kernel 5: per-node cross-attention + intra ----------------
// grid 1152 (= 8 * 144), block 128, 64 nodes per block
__global__ void k_nodeattn(const float* __restrict__ q_w,
                           const float* __restrict__ q_b,
                           const float* __restrict__ sc)
{
    extern __shared__ float sm[];
    float* s_wq   = sm;               // 128*132
    float* s_node = s_wq  + 16896;    // 64*132
    float* s_Q    = s_node + 8448;    // 64*132
    float* s_K    = s_Q   + 8448;     // 16*132
    float* s_V    = s_K   + 2112;
    float* s_H    = s_V   + 2112;
    float* s_sc   = s_H   + 2112;     // 64*16
    float* s_att  = s_sc  + 1024;     // 64*16
    int b  = blockIdx.x / 144;
    int n0 = (blockIdx.x % 144) * 64;
    int tid = threadIdx.x;

    for (int i = tid; i < 16384; i += 128)
        s_wq[(i>>7)*132 + (i&127)] = q_w[i];
    for (int i = tid; i < 8192; i += 128)
        s_node[(i>>7)*132 + (i&127)] = g_node[(b*NN + n0)*CC + i];
    for (int i = tid; i < 2048; i += 128){
        int e = i>>7, c = i&127, o = b*2048 + i;
        s_K[e*132+c] = g_K[o]; s_V[e*132+c] = g_V[o]; s_H[e*132+c] = g_hyperF[o];
    }
    for (int i = tid; i < 1024; i += 128)
        s_sc[i] = sc[(b*NN + n0)*EE + i];
    __syncthreads();

    // Q = node @ q_w^T + q_b   (thread = out channel, 8-node register tile)
    float qb = q_b[tid];
    const float4* wr = (const float4*)(s_wq + tid*132);
    for (int nb = 0; nb < 64; nb += 8){
        float acc[8];
        #pragma unroll
        for (int i=0;i<8;i++) acc[i] = qb;
        for (int kk = 0; kk < 32; kk++){
            float4 w = wr[kk];
            #pragma unroll
            for (int i=0;i<8;i++){
                float4 x = ((const float4*)(s_node + (nb+i)*132))[kk];
                acc[i] += x.x*w.x + x.y*w.y + x.z*w.z + x.w*w.w;
            }
        }
        #pragma unroll
        for (int i=0;i<8;i++) s_Q[(nb+i)*132 + tid] = acc[i];
    }
    __syncthreads();

    // logits = Q @ K^T * C^-0.5
    for (int p = tid; p < 1024; p += 128){
        int n = p>>4, e = p&15;
        const float4* qr = (const float4*)(s_Q + n*132);
        const float4* kr = (const float4*)(s_K + e*132);
        float acc = 0.f;
        for (int kk=0; kk<32; kk++){
            float4 a = qr[kk], k4 = kr[kk];
            acc += a.x*k4.x + a.y*k4.y + a.z*k4.z + a.w*k4.w;
        }
        s_att[p] = acc * 0.08838834764831845f;   // 128^-0.5
    }
    __syncthreads();
    if (tid < 64){
        float* row = s_att + tid*16;
        float mx = row[0];
        #pragma unroll
        for (int e=1;e<16;e++) mx = fmaxf(mx, row[e]);
        float s = 0.f;
        #pragma unroll
        for (int e=0;e<16;e++){ float v = expf(row[e]-mx); row[e]=v; s+=v; }
        float inv = 1.f/s;
        #pragma unroll
        for (int e=0;e<16;e++) row[e] *= inv;
    }
    __syncthreads();

    float vcol[16], hcol[16];
    #pragma unroll
    for (int e=0;e<16;e++){ vcol[e] = s_V[e*132+tid]; hcol[e] = s_H[e*132+tid]; }
    for (int n = 0; n < 64; n++){
        float ac = 0.f, ai = 0.f;
        #pragma unroll
        for (int e=0;e<16;e++){
            ac += s_att[n*16+e]*vcol[e];
            ai += s_sc [n*16+e]*hcol[e];
        }
        int o = (b*NN + n0 + n)*CC + tid;
        g_cross[o] = ac; g_intra[o] = ai;
    }
}

// ---------------- kernel 6: fusion LN + gate ----------------
// grid 2304 (= 8 * 288), block 128, 32 nodes per block
__global__ void k_gate(const float* __restrict__ gate_w, const float* __restrict__ gate_b,
                       const float* __restrict__ nf_g, const float* __restrict__ nf_b,
                       const float* __restrict__ gl_g, const float* __restrict__ gl_b)
{
    extern __shared__ float sm[];
    float* s_gw = sm;             // 128*260
    float* s_cb = s_gw + 33280;   // 32*264 combined
    float* s_gp = s_cb + 8448;    // 32*132
    int b  = blockIdx.x / 288;
    int n0 = (blockIdx.x % 288) * 32;
    int tid = threadIdx.x;

    for (int i = tid; i < 32768; i += 128)
        s_gw[(i>>8)*260 + (i&255)] = gate_w[i];
    for (int i = tid; i < 4096; i += 128){
        int n = i>>7, c = i&127;
        s_cb[n*264 + c]       = g_intra[(b*NN + n0)*CC + i];
        s_cb[n*264 + 128 + c] = g_cross[(b*NN + n0)*CC + i];
    }
    __syncthreads();

    int w = tid >> 5, lane = tid & 31;
    for (int n = w; n < 32; n += 4){                 // LN over 256
        float v[8]; float s = 0.f;
        #pragma unroll
        for (int i=0;i<8;i++){ v[i] = s_cb[n*264 + lane + 32*i]; s += v[i]; }
        for (int o=16;o;o>>=1) s += __shfl_xor_sync(0xffffffffu, s, o);
        float m = s*(1.f/256.f), q = 0.f;
        #pragma unroll
        for (int i=0;i<8;i++){ float d=v[i]-m; q += d*d; }
        for (int o=16;o;o>>=1) q += __shfl_xor_sync(0xffffffffu, q, o);
        float rs = rsqrtf(q*(1.f/256.f)+1e-5f);
        #pragma unroll
        for (int i=0;i<8;i++)
            s_cb[n*264 + lane + 32*i] = (v[i]-m)*rs*nf_g[lane+32*i] + nf_b[lane+32*i];
    }
    __syncthreads();

    float gb = gate_b[tid];
    const float4* wr = (const float4*)(s_gw + tid*260);
    for (int nb = 0; nb < 32; nb += 4){
        float acc[4];
        #pragma unroll
        for (int i=0;i<4;i++) acc[i] = gb;
        for (int kk = 0; kk < 64; kk++){
            float4 ww = wr[kk];
            #pragma unroll
            for (int i=0;i<4;i++){
                float4 x = ((const float4*)(s_cb + (nb+i)*264))[kk];
                acc[i] += x.x*ww.x + x.y*ww.y + x.z*ww.z + x.w*ww.w;
            }
        }
        #pragma unroll
        for (int i=0;i<4;i++) s_gp[(nb+i)*132 + tid] = acc[i];
    }
    __syncthreads();

    for (int n = w; n < 32; n += 4){                 // LN over 128 + sigmoid
        float v[4]; float s = 0.f;
        #pragma unroll
        for (int i=0;i<4;i++){ v[i] = s_gp[n*132 + lane + 32*i]; s += v[i]; }
        for (int o=16;o;o>>=1) s += __shfl_xor_sync(0xffffffffu, s, o);
        float m = s*(1.f/128.f), q = 0.f;
        #pragma unroll
        for (int i=0;i<4;i++){ float d=v[i]-m; q += d*d; }
        for (int o=16;o;o>>=1) q += __shfl_xor_sync(0xffffffffu, q, o);
        float rs = rsqrtf(q*(1.f/128.f)+1e-5f);
        #pragma unroll
        for (int i=0;i<4;i++){
            float z = (v[i]-m)*rs*gl_g[lane+32*i] + gl_b[lane+32*i];
            g_gate[(b*NN + n0 + n)*CC + lane + 32*i] = 1.f/(1.f + expf(-z));
        }
    }
}

// ---------------- kernel 7: fuse + node_proj + gelu + transpose out ----------------
// grid 1152 (= 8 * 144), block 128, 64 nodes per block
__global__ void k_final(const float* __restrict__ nproj_w,
                        const float* __restrict__ nproj_b,
                        float* __restrict__ out)
{
    extern __shared__ float sm[];
    float* s_wn = sm;             // 128*132
    float* s_u  = s_wn + 16896;   // 64*132
    float* s_o  = s_u  + 8448;    // 128*65
    int b  = blockIdx.x / 144;
    int n0 = (blockIdx.x % 144) * 64;
    int tid = threadIdx.x;

    for (int i = tid; i < 16384; i += 128)
        s_wn[(i>>7)*132 + (i&127)] = nproj_w[i];
    for (int i = tid; i < 8192; i += 128){
        int idx = (b*NN + n0)*CC + i;
        float g = g_gate[idx];
        float u = g_node[idx] + g*g_intra[idx] + (1.f - g)*g_cross[idx];
        s_u[(i>>7)*132 + (i&127)] = u;
    }
    __syncthreads();

    float nbias = nproj_b[tid];
    const float4* wr = (const float4*)(s_wn + tid*132);
    for (int nb = 0; nb < 64; nb += 8){
        float acc[8];
        #pragma unroll
        for (int i=0;i<8;i++) acc[i] = nbias;
        for (int kk = 0; kk < 32; kk++){
            float4 w = wr[kk];
            #pragma unroll
            for (int i=0;i<8;i++){
                float4 x = ((const float4*)(s_u + (nb+i)*132))[kk];
                acc[i] += x.x*w.x + x.y*w.y + x.z*w.z + x.w*w.w;
            }
        }
        #pragma unroll
        for (int i=0;i<8;i++) s_o[tid*65 + nb + i] = gelu_exact(acc[i]);
    }
    __syncthreads();

    for (int i = tid; i < 8192; i += 128){
        int c = i>>6, n = i&63;
        out[(b*CC + c)*NN + n0 + n] = s_o[c*65 + n];
    }
}

// ---------------- launch ----------------
extern "C" void kernel_launch(void* const* d_in, const int* in_sizes, int n_in,
                              void* d_out, int out_size)
{
    const float* fm        = (const float*)d_in[0];
    const float* sc        = (const float*)d_in[1];
    const float* np_g      = (const float*)d_in[2];
    const float* np_b      = (const float*)d_in[3];
    const float* mha_w_in  = (const float*)d_in[4];
    const float* mha_b_in  = (const float*)d_in[5];
    const float* mha_w_out = (const float*)d_in[6];
    const float* mha_b_out = (const float*)d_in[7];
    const float* ffn_w1    = (const float*)d_in[8];
    const float* ffn_b1    = (const float*)d_in[9];
    const float* ffn_w2    = (const float*)d_in[10];
    const float* ffn_b2    = (const float*)d_in[11];
    const float* tnorm_g   = (const float*)d_in[12];
    const float* tnorm_b   = (const float*)d_in[13];
    const float* nh_g      = (const float*)d_in[14];
    const float* nh_b      = (const float*)d_in[15];
    const float* hp_w      = (const float*)d_in[16];
    const float* hp_b      = (const float*)d_in[17];
    const float* q_w       = (const float*)d_in[18];
    const float* q_b       = (const float*)d_in[19];
    const float* kv_w      = (const float*)d_in[20];
    const float* kv_b      = (const float*)d_in[21];
    const float* nf_g      = (const float*)d_in[22];
    const float* nf_b      = (const float*)d_in[23];
    const float* gate_w    = (const float*)d_in[24];
    const float* gate_b    = (const float*)d_in[25];
    const float* gl_g      = (const float*)d_in[26];
    const float* gl_b      = (const float*)d_in[27];
    const float* nproj_w   = (const float*)d_in[28];
    const float* nproj_b   = (const float*)d_in[29];

    cudaFuncSetAttribute(k_hyper,    cudaFuncAttributeMaxDynamicSharedMemorySize, 88576);
    cudaFuncSetAttribute(k_nodeattn, cudaFuncAttributeMaxDynamicSharedMemorySize, 168704);
    cudaFuncSetAttribute(k_gate,     cudaFuncAttributeMaxDynamicSharedMemorySize, 183808);
    cudaFuncSetAttribute(k_final,    cudaFuncAttributeMaxDynamicSharedMemorySize, 134656);

    k_node_ln<<<2304, 128>>>(fm, np_g, np_b);
    k_agg<<<288, 128>>>(sc);
    k_reduce<<<16, 1024>>>();
    k_hyper<<<8, 512, 88576>>>(mha_w_in, mha_b_in, mha_w_out, mha_b_out,
                               ffn_w1, ffn_b1, ffn_w2, ffn_b2,
                               tnorm_g, tnorm_b, nh_g, nh_b,
                               hp_w, hp_b, kv_w, kv_b);
    k_nodeattn<<<1152, 128, 168704>>>(q_w, q_b, sc);
    k_gate<<<2304, 128, 183808>>>(gate_w, gate_b, nf_g, nf_b, gl_g, gl_b);
    k_final<<<1152, 128, 134656>>>(nproj_w, nproj_b, (float*)d_out);
}

// round 3
// speedup vs baseline: 2.1815x; 2.1815x over previous
#include <cuda_runtime.h>
#include <math.h>

#define BB 8
#define CC 128
#define NN 9216
#define EE 16

// ---------------- scratch ----------------
__device__ float g_node [BB*NN*CC];
__device__ float g_intra[BB*NN*CC];
__device__ float g_cross[BB*NN*CC];
__device__ float g_gate [BB*NN*CC];
__device__ float g_part [BB*288*EE*CC];
__device__ float g_hyper [BB*EE*CC];
__device__ float g_hyperF[BB*EE*CC];
__device__ float g_V [BB*EE*CC];
__device__ float g_Kp[BB*EE*CC];
__device__ float g_kb[BB*EE];

__device__ __forceinline__ float gelu_exact(float x){
    return 0.5f*x*(1.0f + erff(x*0.70710678118654752f));
}

// ============ kernel 1: transpose + LayerNorm(node) + agg partials ============
// grid 2304 (8*288), block 128, 32 nodes/block
__global__ void k_node_ln(const float* __restrict__ fm,
                          const float* __restrict__ gam,
                          const float* __restrict__ bet,
                          const float* __restrict__ sc)
{
    __shared__ float tile[32*132];
    __shared__ float s_sc[32*16];
    __shared__ float s_mean[32], s_rstd[32];
    int b  = blockIdx.x / 288;
    int n0 = (blockIdx.x % 288) * 32;
    int tid = threadIdx.x;
    for (int i = tid; i < 4096; i += 128){
        int c = i >> 5, n = i & 31;
        tile[n*132 + c] = fm[(b*CC + c)*NN + n0 + n];
    }
    for (int i = tid; i < 512; i += 128)
        s_sc[i] = sc[(b*NN + n0)*EE + i];
    __syncthreads();
    int w = tid >> 5, lane = tid & 31;
    for (int n = w*8; n < w*8 + 8; n++){
        float v0 = tile[n*132+lane],    v1 = tile[n*132+lane+32];
        float v2 = tile[n*132+lane+64], v3 = tile[n*132+lane+96];
        float s = v0+v1+v2+v3;
        for (int o=16;o;o>>=1) s += __shfl_xor_sync(0xffffffffu, s, o);
        float m = s * (1.0f/128.0f);
        float d0=v0-m, d1=v1-m, d2=v2-m, d3=v3-m;
        float q = d0*d0+d1*d1+d2*d2+d3*d3;
        for (int o=16;o;o>>=1) q += __shfl_xor_sync(0xffffffffu, q, o);
        if (lane == 0){ s_mean[n]=m; s_rstd[n]=rsqrtf(q*(1.0f/128.0f)+1e-5f); }
    }
    __syncthreads();
    float gg = gam[tid], bb = bet[tid];
    float acc[16];
    #pragma unroll
    for (int e=0;e<16;e++) acc[e]=0.f;
    for (int n = 0; n < 32; n++){
        float v = (tile[n*132+tid]-s_mean[n])*s_rstd[n]*gg + bb;
        g_node[(b*NN + n0 + n)*CC + tid] = v;
        #pragma unroll
        for (int e=0;e<16;e++) acc[e] += s_sc[n*16+e]*v;
    }
    #pragma unroll
    for (int e=0;e<16;e++)
        g_part[((b*288 + (blockIdx.x%288))*EE + e)*CC + tid] = acc[e];
}

// ============ kernel 2: reduce agg partials ============
__global__ void k_reduce()
{
    int i = blockIdx.x*1024 + threadIdx.x;   // 16384 total
    int b = i >> 11, rem = i & 2047;
    float s = 0.f;
    #pragma unroll 4
    for (int j = 0; j < 288; j++) s += g_part[(b*288 + j)*2048 + rem];
    g_hyper[b*2048 + rem] = s;
}

// ============ kernel 3: hyperedge transformer pipeline ============
// grid 8, block 512. Full-weight smem staging per GEMM.
template<int CIN, int COUT, int ACT>
__device__ __forceinline__ void gemmF(const float* __restrict__ W,
                                      const float* __restrict__ bias,
                                      const float* in, int inPitch,
                                      float* out, int outPitch, float* sw)
{
    const int pitch = CIN + 4;
    const int cin4  = CIN >> 2;
    const float4* W4 = (const float4*)W;
    for (int i = threadIdx.x; i < (COUT*CIN)>>2; i += 512){
        int r = i / cin4, c4 = i - r*cin4;
        ((float4*)(sw + r*pitch))[c4] = W4[i];
    }
    __syncthreads();
    const int logC  = (COUT == 256) ? 8 : 7;
    const int estep = 512 >> logC;      // 2 or 4
    const int nE    = 16 / estep;       // 8 or 4
    int j  = threadIdx.x & (COUT-1);
    int e0 = threadIdx.x >> logC;
    const float4* wr = (const float4*)(sw + j*pitch);
    float acc[nE];
    const float4* ar[nE];
    #pragma unroll
    for (int r=0;r<nE;r++){ acc[r]=0.f; ar[r]=(const float4*)(in + (e0 + r*estep)*inPitch); }
    for (int kk = 0; kk < cin4; kk++){
        float4 wv = wr[kk];
        #pragma unroll
        for (int r=0;r<nE;r++){
            float4 av = ar[r][kk];
            acc[r] += av.x*wv.x + av.y*wv.y + av.z*wv.z + av.w*wv.w;
        }
    }
    float bj = bias[j];
    #pragma unroll
    for (int r=0;r<nE;r++){
        float v = acc[r] + bj;
        if (ACT) v = gelu_exact(v);
        out[(e0 + r*estep)*outPitch + j] = v;
    }
    __syncthreads();
}

__device__ __forceinline__ void ln16_128(const float* a, const float* r, int pitch,
                                         const float* __restrict__ g,
                                         const float* __restrict__ b,
                                         float* out, int outPitch)
{
    int w = threadIdx.x >> 5, lane = threadIdx.x & 31;
    if (w < 16){
        float v[4]; float s = 0.f;
        #pragma unroll
        for (int i=0;i<4;i++){
            float x = a[w*pitch + lane + 32*i];
            if (r) x += r[w*pitch + lane + 32*i];
            v[i] = x; s += x;
        }
        for (int o=16;o;o>>=1) s += __shfl_xor_sync(0xffffffffu, s, o);
        float m = s*(1.f/128.f), q = 0.f;
        #pragma unroll
        for (int i=0;i<4;i++){ float d=v[i]-m; q += d*d; }
        for (int o=16;o;o>>=1) q += __shfl_xor_sync(0xffffffffu, q, o);
        float rs = rsqrtf(q*(1.f/128.f)+1e-5f);
        #pragma unroll
        for (int i=0;i<4;i++)
            out[w*outPitch + lane + 32*i] = (v[i]-m)*rs*g[lane+32*i] + b[lane+32*i];
    }
    __syncthreads();
}

__global__ void __launch_bounds__(512)
k_hyper(const float* __restrict__ mha_w_in, const float* __restrict__ mha_b_in,
        const float* __restrict__ mha_w_out, const float* __restrict__ mha_b_out,
        const float* __restrict__ ffn_w1, const float* __restrict__ ffn_b1,
        const float* __restrict__ ffn_w2, const float* __restrict__ ffn_b2,
        const float* __restrict__ tnorm_g, const float* __restrict__ tnorm_b,
        const float* __restrict__ nh_g, const float* __restrict__ nh_b,
        const float* __restrict__ hp_w, const float* __restrict__ hp_b,
        const float* __restrict__ kv_w, const float* __restrict__ kv_b,
        const float* __restrict__ q_w, const float* __restrict__ q_b)
{
    extern __shared__ float sm[];
    float* s0   = sm;            // 16*132
    float* s1   = s0 + 2112;
    float* s2   = s1 + 2112;
    float* s3   = s2 + 2112;
    float* sh   = s3 + 2112;     // 16*264
    float* satt = sh + 4224;     // 1024
    float* sw   = satt + 1024;   // 256*132 = 33792 max
    int b = blockIdx.x, tid = threadIdx.x;

    for (int i = tid; i < 2048; i += 512)
        s0[(i>>7)*132 + (i&127)] = g_hyper[b*2048 + i];
    __syncthreads();

    gemmF<128,128,0>(mha_w_in,           mha_b_in,     s0,132, s1,132, sw);  // q
    gemmF<128,128,0>(mha_w_in + 128*128, mha_b_in+128, s0,132, s2,132, sw);  // k
    gemmF<128,128,0>(mha_w_in + 256*128, mha_b_in+256, s0,132, s3,132, sw);  // v

    for (int p = tid; p < 1024; p += 512){
        int h = p>>8, e1 = (p>>4)&15, e2 = p&15;
        const float* qr = s1 + e1*132 + h*32;
        const float* kr = s2 + e2*132 + h*32;
        float acc = 0.f;
        #pragma unroll
        for (int d=0; d<32; d++) acc += qr[d]*kr[d];
        satt[p] = acc * 0.17677669529663687f;
    }
    __syncthreads();
    if (tid < 64){
        float* row = satt + tid*16;
        float mx = row[0];
        #pragma unroll
        for (int e=1;e<16;e++) mx = fmaxf(mx, row[e]);
        float s = 0.f;
        #pragma unroll
        for (int e=0;e<16;e++){ float v = expf(row[e]-mx); row[e]=v; s+=v; }
        float inv = 1.f/s;
        #pragma unroll
        for (int e=0;e<16;e++) row[e] *= inv;
    }
    __syncthreads();
    for (int p = tid; p < 2048; p += 512){  // ao -> s1
        int e = p>>7, c = p&127, h = c>>5;
        float acc = 0.f;
        #pragma unroll
        for (int e2=0;e2<16;e2++) acc += satt[(h*16+e)*16 + e2] * s3[e2*132 + c];
        s1[e*132 + c] = acc;
    }
    __syncthreads();
    gemmF<128,128,0>(mha_w_out, mha_b_out, s1,132, s2,132, sw);  // attn proj
    ln16_128(s0, s2, 132, tnorm_g, tnorm_b, s3, 132);            // x = LN(hyper+ao)
    gemmF<128,256,1>(ffn_w1, ffn_b1, s3,132, sh,264, sw);        // hidden (gelu)
    gemmF<256,128,0>(ffn_w2, ffn_b2, sh,264, s1,132, sw);        // ffn out
    ln16_128(s3, s1, 132, tnorm_g, tnorm_b, s2, 132);            // hyper2
    ln16_128(s2, (const float*)0, 132, nh_g, nh_b, s3, 132);     // hyper3
    gemmF<128,128,1>(hp_w, hp_b, s3,132, s0,132, sw);            // hyperF
    gemmF<128,128,0>(kv_w,           kv_b,     s0,132, s1,132, sw);  // K -> s1
    gemmF<128,128,0>(kv_w + 128*128, kv_b+128, s0,132, s2,132, sw);  // V -> s2

    // stage q_w, compute Kp[e][k] = sum_c K[e][c] q_w[c][k]  (pre-scaled)
    {
        const float4* W4 = (const float4*)q_w;
        for (int i = tid; i < 4096; i += 512){
            int r = i >> 5, c4 = i & 31;
            ((float4*)(sw + r*132))[c4] = W4[i];
        }
        __syncthreads();
        const float scl = 0.08838834764831845f; // 128^-0.5
        for (int o = tid; o < 2048; o += 512){
            int e = o>>7, k = o&127;
            float acc = 0.f;
            for (int c = 0; c < 128; c++) acc += s1[e*132+c]*sw[c*132+k];
            g_Kp[b*2048 + o] = acc * scl;
        }
        if (tid < 16){
            float acc = 0.f;
            for (int c = 0; c < 128; c++) acc += q_b[c]*s1[tid*132+c];
            g_kb[b*16 + tid] = acc * scl;
        }
    }

    for (int i = tid; i < 2048; i += 512){
        int e = i>>7, c = i&127, o = b*2048 + i;
        g_hyperF[o] = s0[e*132+c];
        g_V[o]      = s2[e*132+c];
    }
}

// ============ kernel 4: per-node attention (no Q GEMM) + intra ============
// grid 576 (8*72), block 256, 128 nodes/block
__global__ void __launch_bounds__(256)
k_nodeattn(const float* __restrict__ sc)
{
    extern __shared__ float sm[];
    float* s_node = sm;              // 128*132
    float* s_Kp   = s_node + 16896;  // 16*132
    float* s_V    = s_Kp  + 2112;
    float* s_H    = s_V   + 2112;
    float* s_sc   = s_H   + 2112;    // 128*16
    float* s_att  = s_sc  + 2048;    // 128*16
    float* s_kb   = s_att + 2048;    // 16
    int b  = blockIdx.x / 72;
    int n0 = (blockIdx.x % 72) * 128;
    int tid = threadIdx.x;

    for (int i4 = tid; i4 < 4096; i4 += 256){
        int n = i4 >> 5, c4 = i4 & 31;
        ((float4*)(s_node + n*132))[c4] =
            ((const float4*)(g_node + (size_t)(b*NN + n0 + n)*CC))[c4];
    }
    for (int i = tid; i < 2048; i += 256){
        int e = i>>7, c = i&127, o = b*2048 + i;
        s_Kp[e*132+c] = g_Kp[o]; s_V[e*132+c] = g_V[o]; s_H[e*132+c] = g_hyperF[o];
    }
    for (int i = tid; i < 2048; i += 256)
        s_att[i] = 0.f, s_sc[i] = sc[(b*NN + n0)*EE + i];
    if (tid < 16) s_kb[tid] = g_kb[b*16 + tid];
    __syncthreads();

    // logits[n][e] = node[n] . Kp[e] + kb[e]
    for (int p = tid; p < 2048; p += 256){
        int n = p>>4, e = p&15;
        const float4* nr = (const float4*)(s_node + n*132);
        const float4* kr = (const float4*)(s_Kp  + e*132);
        float acc = 0.f;
        for (int kk = 0; kk < 32; kk++){
            float4 a = nr[kk], k4 = kr[kk];
            acc += a.x*k4.x + a.y*k4.y + a.z*k4.z + a.w*k4.w;
        }
        s_att[p] = acc + s_kb[e];
    }
    __syncthreads();
    if (tid < 128){
        float* row = s_att + tid*16;
        float mx = row[0];
        #pragma unroll
        for (int e=1;e<16;e++) mx = fmaxf(mx, row[e]);
        float s = 0.f;
        #pragma unroll
        for (int e=0;e<16;e++){ float v = expf(row[e]-mx); row[e]=v; s+=v; }
        float inv = 1.f/s;
        #pragma unroll
        for (int e=0;e<16;e++) row[e] *= inv;
    }
    __syncthreads();

    int c = tid & 127, g = tid >> 7;
    float vcol[16], hcol[16];
    #pragma unroll
    for (int e=0;e<16;e++){ vcol[e] = s_V[e*132+c]; hcol[e] = s_H[e*132+c]; }
    for (int n = g*64; n < g*64 + 64; n++){
        float ac = 0.f, ai = 0.f;
        #pragma unroll
        for (int e=0;e<16;e++){
            ac += s_att[n*16+e]*vcol[e];
            ai += s_sc [n*16+e]*hcol[e];
        }
        size_t o = (size_t)(b*NN + n0 + n)*CC + c;
        g_cross[o] = ac; g_intra[o] = ai;
    }
}

// ============ kernel 5: fusion LN + gate ============
// grid 1152 (8*144), block 256, 64 nodes/block
__global__ void __launch_bounds__(256)
k_gate(const float* __restrict__ gate_w, const float* __restrict__ gate_b,
       const float* __restrict__ nf_g, const float* __restrict__ nf_b,
       const float* __restrict__ gl_g, const float* __restrict__ gl_b)
{
    extern __shared__ float sm[];
    float* s_w  = sm;             // 64*260
    float* s_cb = s_w + 16640;    // 64*264
    float* s_gp = s_cb + 16896;   // 64*132
    int b  = blockIdx.x / 144;
    int n0 = (blockIdx.x % 144) * 64;
    int tid = threadIdx.x;

    for (int i4 = tid; i4 < 2048; i4 += 256){
        int n = i4 >> 5, c4 = i4 & 31;
        size_t base = (size_t)(b*NN + n0 + n)*CC;
        ((float4*)(s_cb + n*264))[c4]       = ((const float4*)(g_intra + base))[c4];
        ((float4*)(s_cb + n*264 + 128))[c4] = ((const float4*)(g_cross + base))[c4];
    }
    __syncthreads();

    int w = tid >> 5, lane = tid & 31;
    for (int n = w; n < 64; n += 8){            // LN over 256
        float v[8]; float s = 0.f;
        #pragma unroll
        for (int i=0;i<8;i++){ v[i] = s_cb[n*264 + lane + 32*i]; s += v[i]; }
        for (int o=16;o;o>>=1) s += __shfl_xor_sync(0xffffffffu, s, o);
        float m = s*(1.f/256.f), q = 0.f;
        #pragma unroll
        for (int i=0;i<8;i++){ float d=v[i]-m; q += d*d; }
        for (int o=16;o;o>>=1) q += __shfl_xor_sync(0xffffffffu, q, o);
        float rs = rsqrtf(q*(1.f/256.f)+1e-5f);
        #pragma unroll
        for (int i=0;i<8;i++)
            s_cb[n*264 + lane + 32*i] = (v[i]-m)*rs*nf_g[lane+32*i] + nf_b[lane+32*i];
    }
    __syncthreads();

    for (int chunk = 0; chunk < 2; chunk++){
        int c0 = chunk * 64;
        for (int i4 = tid; i4 < 4096; i4 += 256){
            int r = i4 >> 6, k4 = i4 & 63;
            ((float4*)(s_w + r*260))[k4] = ((const float4*)(gate_w + (size_t)(c0+r)*256))[k4];
        }
        __syncthreads();
        int cl = tid & 63, g = tid >> 6;           // g in 0..3 -> 16 nodes each
        const float4* wr = (const float4*)(s_w + cl*260);
        float gb = gate_b[c0 + cl];
        for (int t2 = 0; t2 < 2; t2++){
            int nb = g*16 + t2*8;
            float acc[8];
            #pragma unroll
            for (int i=0;i<8;i++) acc[i] = gb;
            for (int kk = 0; kk < 64; kk++){
                float4 wv = wr[kk];
                #pragma unroll
                for (int i=0;i<8;i++){
                    float4 a = ((const float4*)(s_cb + (nb+i)*264))[kk];
                    acc[i] += a.x*wv.x + a.y*wv.y + a.z*wv.z + a.w*wv.w;
                }
            }
            #pragma unroll
            for (int i=0;i<8;i++) s_gp[(nb+i)*132 + c0 + cl] = acc[i];
        }
        __syncthreads();
    }

    for (int n = w; n < 64; n += 8){            // LN over 128 + sigmoid
        float v[4]; float s = 0.f;
        #pragma unroll
        for (int i=0;i<4;i++){ v[i] = s_gp[n*132 + lane + 32*i]; s += v[i]; }
        for (int o=16;o;o>>=1) s += __shfl_xor_sync(0xffffffffu, s, o);
        float m = s*(1.f/128.f), q = 0.f;
        #pragma unroll
        for (int i=0;i<4;i++){ float d=v[i]-m; q += d*d; }
        for (int o=16;o;o>>=1) q += __shfl_xor_sync(0xffffffffu, q, o);
        float rs = rsqrtf(q*(1.f/128.f)+1e-5f);
        #pragma unroll
        for (int i=0;i<4;i++){
            float z = (v[i]-m)*rs*gl_g[lane+32*i] + gl_b[lane+32*i];
            g_gate[(size_t)(b*NN + n0 + n)*CC + lane + 32*i] = 1.f/(1.f + expf(-z));
        }
    }
}

// ============ kernel 6: fuse + node_proj + gelu + transpose out ============
// grid 1152 (8*144), block 256, 64 nodes/block
__global__ void __launch_bounds__(256)
k_final(const float* __restrict__ nproj_w,
        const float* __restrict__ nproj_b,
        float* __restrict__ out)
{
    extern __shared__ float sm[];
    float* s_wn = sm;             // 128*132
    float* s_u  = s_wn + 16896;   // 64*132
    float* s_o  = s_u  + 8448;    // 128*68
    int b  = blockIdx.x / 144;
    int n0 = (blockIdx.x % 144) * 64;
    int tid = threadIdx.x;

    for (int i4 = tid; i4 < 4096; i4 += 256){
        int r = i4 >> 5, k4 = i4 & 31;
        ((float4*)(s_wn + r*132))[k4] = ((const float4*)nproj_w)[i4];
    }
    for (int i4 = tid; i4 < 2048; i4 += 256){
        int n = i4 >> 5, c4 = i4 & 31;
        size_t base = (size_t)(b*NN + n0 + n)*CC;
        float4 nd = ((const float4*)(g_node  + base))[c4];
        float4 gt = ((const float4*)(g_gate  + base))[c4];
        float4 it = ((const float4*)(g_intra + base))[c4];
        float4 cr = ((const float4*)(g_cross + base))[c4];
        float4 u;
        u.x = nd.x + gt.x*it.x + (1.f-gt.x)*cr.x;
        u.y = nd.y + gt.y*it.y + (1.f-gt.y)*cr.y;
        u.z = nd.z + gt.z*it.z + (1.f-gt.z)*cr.z;
        u.w = nd.w + gt.w*it.w + (1.f-gt.w)*cr.w;
        ((float4*)(s_u + n*132))[c4] = u;
    }
    __syncthreads();

    int c = tid & 127, g = tid >> 7;
    const float4* wr = (const float4*)(s_wn + c*132);
    float nbias = nproj_b[c];
    for (int t = 0; t < 4; t++){
        int nb = g*32 + t*8;
        float acc[8];
        #pragma unroll
        for (int i=0;i<8;i++) acc[i] = nbias;
        for (int kk = 0; kk < 32; kk++){
            float4 wv = wr[kk];
            #pragma unroll
            for (int i=0;i<8;i++){
                float4 a = ((const float4*)(s_u + (nb+i)*132))[kk];
                acc[i] += a.x*wv.x + a.y*wv.y + a.z*wv.z + a.w*wv.w;
            }
        }
        #pragma unroll
        for (int i=0;i<8;i++) s_o[c*68 + nb + i] = gelu_exact(acc[i]);
    }
    __syncthreads();

    for (int i = tid; i < 8192; i += 256){
        int c2 = i >> 6, n = i & 63;
        out[(size_t)(b*CC + c2)*NN + n0 + n] = s_o[c2*68 + n];
    }
}

// ---------------- launch ----------------
extern "C" void kernel_launch(void* const* d_in, const int* in_sizes, int n_in,
                              void* d_out, int out_size)
{
    const float* fm        = (const float*)d_in[0];
    const float* sc        = (const float*)d_in[1];
    const float* np_g      = (const float*)d_in[2];
    const float* np_b      = (const float*)d_in[3];
    const float* mha_w_in  = (const float*)d_in[4];
    const float* mha_b_in  = (const float*)d_in[5];
    const float* mha_w_out = (const float*)d_in[6];
    const float* mha_b_out = (const float*)d_in[7];
    const float* ffn_w1    = (const float*)d_in[8];
    const float* ffn_b1    = (const float*)d_in[9];
    const float* ffn_w2    = (const float*)d_in[10];
    const float* ffn_b2    = (const float*)d_in[11];
    const float* tnorm_g   = (const float*)d_in[12];
    const float* tnorm_b   = (const float*)d_in[13];
    const float* nh_g      = (const float*)d_in[14];
    const float* nh_b      = (const float*)d_in[15];
    const float* hp_w      = (const float*)d_in[16];
    const float* hp_b      = (const float*)d_in[17];
    const float* q_w       = (const float*)d_in[18];
    const float* q_b       = (const float*)d_in[19];
    const float* kv_w      = (const float*)d_in[20];
    const float* kv_b      = (const float*)d_in[21];
    const float* nf_g      = (const float*)d_in[22];
    const float* nf_b      = (const float*)d_in[23];
    const float* gate_w    = (const float*)d_in[24];
    const float* gate_b    = (const float*)d_in[25];
    const float* gl_g      = (const float*)d_in[26];
    const float* gl_b      = (const float*)d_in[27];
    const float* nproj_w   = (const float*)d_in[28];
    const float* nproj_b   = (const float*)d_in[29];

    // dynamic smem sizes (bytes)
    const int smem_hyper    = (2112*4 + 4224 + 1024 + 33792) * 4;   // 189952
    const int smem_nodeattn = (16896 + 2112*3 + 2048 + 2048 + 16) * 4; // 109440
    const int smem_gate     = (16640 + 16896 + 8448) * 4;           // 167936
    const int smem_final    = (16896 + 8448 + 128*68) * 4;          // 136192

    cudaFuncSetAttribute(k_hyper,    cudaFuncAttributeMaxDynamicSharedMemorySize, smem_hyper);
    cudaFuncSetAttribute(k_nodeattn, cudaFuncAttributeMaxDynamicSharedMemorySize, smem_nodeattn);
    cudaFuncSetAttribute(k_gate,     cudaFuncAttributeMaxDynamicSharedMemorySize, smem_gate);
    cudaFuncSetAttribute(k_final,    cudaFuncAttributeMaxDynamicSharedMemorySize, smem_final);

    k_node_ln<<<2304, 128>>>(fm, np_g, np_b, sc);
    k_reduce<<<16, 1024>>>();
    k_hyper<<<8, 512, smem_hyper>>>(mha_w_in, mha_b_in, mha_w_out, mha_b_out,
                                    ffn_w1, ffn_b1, ffn_w2, ffn_b2,
                                    tnorm_g, tnorm_b, nh_g, nh_b,
                                    hp_w, hp_b, kv_w, kv_b, q_w, q_b);
    k_nodeattn<<<576, 256, smem_nodeattn>>>(sc);
    k_gate<<<1152, 256, smem_gate>>>(gate_w, gate_b, nf_g, nf_b, gl_g, gl_b);
    k_final<<<1152, 256, smem_final>>>(nproj_w, nproj_b, (float*)d_out);
}

// round 4
// speedup vs baseline: 3.4305x; 1.5725x over previous
#include <cuda_runtime.h>
#include <math.h>

#define BB 8
#define CC 128
#define NN 9216
#define EE 16

// ---------------- scratch ----------------
__device__ float g_node [BB*NN*CC];
__device__ float g_part [BB*288*EE*CC];
__device__ float g_hyper [BB*EE*CC];
__device__ float g_hyperF[BB*EE*CC];
__device__ float g_V [BB*EE*CC];
__device__ float g_Kp[BB*EE*CC];
__device__ float g_kb[BB*EE];
__device__ float g_Hw[BB*EE*CC];
__device__ float g_Vw[BB*EE*CC];
__device__ float g_GH[BB*EE*EE];
__device__ float g_GV[BB*EE*EE];
__device__ float g_hs[BB*EE];
__device__ float g_vs[BB*EE];
__device__ float g_u[CC];
__device__ float g_t[CC];

__device__ __forceinline__ float gelu_exact(float x){
    return 0.5f*x*(1.0f + erff(x*0.70710678118654752f));
}

// ============ kernel 1: transpose + LayerNorm(node) + agg partials ============
__global__ void k_node_ln(const float* __restrict__ fm,
                          const float* __restrict__ gam,
                          const float* __restrict__ bet,
                          const float* __restrict__ sc)
{
    __shared__ float tile[32*132];
    __shared__ float s_sc[32*16];
    __shared__ float s_mean[32], s_rstd[32];
    int b  = blockIdx.x / 288;
    int n0 = (blockIdx.x % 288) * 32;
    int tid = threadIdx.x;
    for (int i = tid; i < 4096; i += 128){
        int c = i >> 5, n = i & 31;
        tile[n*132 + c] = fm[(b*CC + c)*NN + n0 + n];
    }
    for (int i = tid; i < 512; i += 128)
        s_sc[i] = sc[(b*NN + n0)*EE + i];
    __syncthreads();
    int w = tid >> 5, lane = tid & 31;
    for (int n = w*8; n < w*8 + 8; n++){
        float v0 = tile[n*132+lane],    v1 = tile[n*132+lane+32];
        float v2 = tile[n*132+lane+64], v3 = tile[n*132+lane+96];
        float s = v0+v1+v2+v3;
        for (int o=16;o;o>>=1) s += __shfl_xor_sync(0xffffffffu, s, o);
        float m = s * (1.0f/128.0f);
        float d0=v0-m, d1=v1-m, d2=v2-m, d3=v3-m;
        float q = d0*d0+d1*d1+d2*d2+d3*d3;
        for (int o=16;o;o>>=1) q += __shfl_xor_sync(0xffffffffu, q, o);
        if (lane == 0){ s_mean[n]=m; s_rstd[n]=rsqrtf(q*(1.0f/128.0f)+1e-5f); }
    }
    __syncthreads();
    float gg = gam[tid], bb = bet[tid];
    float acc[16];
    #pragma unroll
    for (int e=0;e<16;e++) acc[e]=0.f;
    for (int n = 0; n < 32; n++){
        float v = (tile[n*132+tid]-s_mean[n])*s_rstd[n]*gg + bb;
        g_node[(size_t)(b*NN + n0 + n)*CC + tid] = v;
        #pragma unroll
        for (int e=0;e<16;e++) acc[e] += s_sc[n*16+e]*v;
    }
    #pragma unroll
    for (int e=0;e<16;e++)
        g_part[((size_t)(b*288 + (blockIdx.x%288))*EE + e)*CC + tid] = acc[e];
}

// ============ kernel 2: reduce agg partials (parallel across 128 SMs) ============
__global__ void k_reduce()
{
    int b = blockIdx.x >> 4, ch = blockIdx.x & 15;
    int c = ch*128 + threadIdx.x;
    float s = 0.f;
    #pragma unroll 4
    for (int j = 0; j < 288; j++) s += g_part[(size_t)(b*288 + j)*2048 + c];
    g_hyper[b*2048 + c] = s;
}

// ============ kernel 3: hyperedge transformer + per-batch precomputes ============
template<int CIN, int COUT, int ACT>
__device__ __forceinline__ void gemmF(const float* __restrict__ W,
                                      const float* __restrict__ bias,
                                      const float* in, int inPitch,
                                      float* out, int outPitch, float* sw)
{
    const int pitch = CIN + 4;
    const int cin4  = CIN >> 2;
    const float4* W4 = (const float4*)W;
    for (int i = threadIdx.x; i < (COUT*CIN)>>2; i += 512){
        int r = i / cin4, c4 = i - r*cin4;
        ((float4*)(sw + r*pitch))[c4] = W4[i];
    }
    __syncthreads();
    const int logC  = (COUT == 256) ? 8 : 7;
    const int estep = 512 >> logC;
    const int nE    = 16 / estep;
    int j  = threadIdx.x & (COUT-1);
    int e0 = threadIdx.x >> logC;
    const float4* wr = (const float4*)(sw + j*pitch);
    float acc[nE];
    const float4* ar[nE];
    #pragma unroll
    for (int r=0;r<nE;r++){ acc[r]=0.f; ar[r]=(const float4*)(in + (e0 + r*estep)*inPitch); }
    for (int kk = 0; kk < cin4; kk++){
        float4 wv = wr[kk];
        #pragma unroll
        for (int r=0;r<nE;r++){
            float4 av = ar[r][kk];
            acc[r] += av.x*wv.x + av.y*wv.y + av.z*wv.z + av.w*wv.w;
        }
    }
    float bj = bias[j];
    #pragma unroll
    for (int r=0;r<nE;r++){
        float v = acc[r] + bj;
        if (ACT) v = gelu_exact(v);
        out[(e0 + r*estep)*outPitch + j] = v;
    }
    __syncthreads();
}

__device__ __forceinline__ void ln16_128(const float* a, const float* r, int pitch,
                                         const float* __restrict__ g,
                                         const float* __restrict__ b,
                                         float* out, int outPitch)
{
    int w = threadIdx.x >> 5, lane = threadIdx.x & 31;
    if (w < 16){
        float v[4]; float s = 0.f;
        #pragma unroll
        for (int i=0;i<4;i++){
            float x = a[w*pitch + lane + 32*i];
            if (r) x += r[w*pitch + lane + 32*i];
            v[i] = x; s += x;
        }
        for (int o=16;o;o>>=1) s += __shfl_xor_sync(0xffffffffu, s, o);
        float m = s*(1.f/128.f), q = 0.f;
        #pragma unroll
        for (int i=0;i<4;i++){ float d=v[i]-m; q += d*d; }
        for (int o=16;o;o>>=1) q += __shfl_xor_sync(0xffffffffu, q, o);
        float rs = rsqrtf(q*(1.f/128.f)+1e-5f);
        #pragma unroll
        for (int i=0;i<4;i++)
            out[w*outPitch + lane + 32*i] = (v[i]-m)*rs*g[lane+32*i] + b[lane+32*i];
    }
    __syncthreads();
}

__global__ void __launch_bounds__(512)
k_hyper(const float* __restrict__ mha_w_in, const float* __restrict__ mha_b_in,
        const float* __restrict__ mha_w_out, const float* __restrict__ mha_b_out,
        const float* __restrict__ ffn_w1, const float* __restrict__ ffn_b1,
        const float* __restrict__ ffn_w2, const float* __restrict__ ffn_b2,
        const float* __restrict__ tnorm_g, const float* __restrict__ tnorm_b,
        const float* __restrict__ nh_g, const float* __restrict__ nh_b,
        const float* __restrict__ hp_w, const float* __restrict__ hp_b,
        const float* __restrict__ kv_w, const float* __restrict__ kv_b,
        const float* __restrict__ q_w, const float* __restrict__ q_b,
        const float* __restrict__ gate_w, const float* __restrict__ gate_b,
        const float* __restrict__ nf_g, const float* __restrict__ nf_b)
{
    extern __shared__ float sm[];
    float* s0   = sm;            // 16*132
    float* s1   = s0 + 2112;
    float* s2   = s1 + 2112;
    float* s3   = s2 + 2112;
    float* sh   = s3 + 2112;     // 16*264
    float* satt = sh + 4224;     // 1024
    float* sw   = satt + 1024;   // 33792 floats
    int b = blockIdx.x, tid = threadIdx.x;

    for (int i = tid; i < 2048; i += 512)
        s0[(i>>7)*132 + (i&127)] = g_hyper[b*2048 + i];
    __syncthreads();

    gemmF<128,128,0>(mha_w_in,           mha_b_in,     s0,132, s1,132, sw);  // q
    gemmF<128,128,0>(mha_w_in + 128*128, mha_b_in+128, s0,132, s2,132, sw);  // k
    gemmF<128,128,0>(mha_w_in + 256*128, mha_b_in+256, s0,132, s3,132, sw);  // v

    for (int p = tid; p < 1024; p += 512){
        int h = p>>8, e1 = (p>>4)&15, e2 = p&15;
        const float* qr = s1 + e1*132 + h*32;
        const float* kr = s2 + e2*132 + h*32;
        float acc = 0.f;
        #pragma unroll
        for (int d=0; d<32; d++) acc += qr[d]*kr[d];
        satt[p] = acc * 0.17677669529663687f;
    }
    __syncthreads();
    if (tid < 64){
        float* row = satt + tid*16;
        float mx = row[0];
        #pragma unroll
        for (int e=1;e<16;e++) mx = fmaxf(mx, row[e]);
        float s = 0.f;
        #pragma unroll
        for (int e=0;e<16;e++){ float v = expf(row[e]-mx); row[e]=v; s+=v; }
        float inv = 1.f/s;
        #pragma unroll
        for (int e=0;e<16;e++) row[e] *= inv;
    }
    __syncthreads();
    for (int p = tid; p < 2048; p += 512){
        int e = p>>7, c = p&127, h = c>>5;
        float acc = 0.f;
        #pragma unroll
        for (int e2=0;e2<16;e2++) acc += satt[(h*16+e)*16 + e2] * s3[e2*132 + c];
        s1[e*132 + c] = acc;
    }
    __syncthreads();
    gemmF<128,128,0>(mha_w_out, mha_b_out, s1,132, s2,132, sw);
    ln16_128(s0, s2, 132, tnorm_g, tnorm_b, s3, 132);
    gemmF<128,256,1>(ffn_w1, ffn_b1, s3,132, sh,264, sw);
    gemmF<256,128,0>(ffn_w2, ffn_b2, sh,264, s1,132, sw);
    ln16_128(s3, s1, 132, tnorm_g, tnorm_b, s2, 132);
    ln16_128(s2, (const float*)0, 132, nh_g, nh_b, s3, 132);
    gemmF<128,128,1>(hp_w, hp_b, s3,132, s0,132, sw);               // H -> s0
    gemmF<128,128,0>(kv_w,           kv_b,     s0,132, s1,132, sw); // K -> s1
    gemmF<128,128,0>(kv_w + 128*128, kv_b+128, s0,132, s2,132, sw); // V -> s2

    // Kp[e,c] = sum_j K[e,j] q_w[j,c] (pre-scaled); kb[e] = scl * q_b . K[e]
    {
        const float4* W4 = (const float4*)q_w;
        for (int i = tid; i < 4096; i += 512){
            int r = i >> 5, c4 = i & 31;
            ((float4*)(sw + r*132))[c4] = W4[i];
        }
        __syncthreads();
        const float scl = 0.08838834764831845f;
        for (int o = tid; o < 2048; o += 512){
            int e = o>>7, k = o&127;
            float acc = 0.f;
            for (int c = 0; c < 128; c++) acc += s1[e*132+c]*sw[c*132+k];
            g_Kp[b*2048 + o] = acc * scl;
        }
        if (tid < 16){
            float acc = 0.f;
            for (int c = 0; c < 128; c++) acc += q_b[c]*s1[tid*132+c];
            g_kb[b*16 + tid] = acc * scl;
        }
    }
    __syncthreads();

    // ---- gate decomposition precomputes ----
    // stage raw gate_w [128][256] into sw pitch 264
    {
        const float4* GW4 = (const float4*)gate_w;
        for (int i = tid; i < 8192; i += 512){
            int r = i >> 6, c4 = i & 63;
            ((float4*)(sw + r*264))[c4] = GW4[i];
        }
        __syncthreads();
        if (tid < 128){
            float t = gate_b[tid];
            for (int c = 0; c < 256; c++) t += nf_b[c]*sw[tid*264+c];
            g_t[tid] = t;
        }
        __syncthreads();
        for (int i = tid; i < 32768; i += 512){
            int r = i >> 8, c = i & 255;
            sw[r*264+c] *= nf_g[c];
        }
        __syncthreads();
        if (tid < 128){
            float u = 0.f;
            for (int c = 0; c < 256; c++) u += sw[tid*264+c];
            g_u[tid] = u;
        }
        // Hw[e,j] / Vw[e,j]
        for (int p = tid; p < 2048; p += 512){
            int j = p & 127, e = p >> 7;
            const float4* hr = (const float4*)(s0 + e*132);
            const float4* vr = (const float4*)(s2 + e*132);
            const float4* w1 = (const float4*)(sw + j*264);
            const float4* w2 = (const float4*)(sw + j*264 + 128);
            float a1 = 0.f, a2 = 0.f;
            #pragma unroll 8
            for (int kk = 0; kk < 32; kk++){
                float4 h = hr[kk], w = w1[kk];
                a1 += h.x*w.x + h.y*w.y + h.z*w.z + h.w*w.w;
                float4 v = vr[kk], x = w2[kk];
                a2 += v.x*x.x + v.y*x.y + v.z*x.z + v.w*x.w;
            }
            g_Hw[b*2048+p] = a1; g_Vw[b*2048+p] = a2;
        }
        // Gram matrices + row sums
        if (tid < 512){
            int q = tid;
            const float* A = (q < 256) ? s0 : s2;
            int qq = q & 255;
            int e = qq >> 4, f = qq & 15;
            const float4* r1 = (const float4*)(A + e*132);
            const float4* r2 = (const float4*)(A + f*132);
            float acc = 0.f;
            #pragma unroll 8
            for (int kk = 0; kk < 32; kk++){
                float4 a = r1[kk], c = r2[kk];
                acc += a.x*c.x + a.y*c.y + a.z*c.z + a.w*c.w;
            }
            if (q < 256) g_GH[b*256+qq] = acc; else g_GV[b*256+qq] = acc;
        }
        if (tid < 32){
            int e = tid & 15;
            const float* A = (tid < 16) ? s0 : s2;
            float s = 0.f;
            for (int c = 0; c < 128; c++) s += A[e*132+c];
            if (tid < 16) g_hs[b*16+e] = s; else g_vs[b*16+e] = s;
        }
    }

    for (int i = tid; i < 2048; i += 512){
        int e = i>>7, c = i&127, o = b*2048 + i;
        g_hyperF[o] = s0[e*132+c];
        g_V[o]      = s2[e*132+c];
    }
}

// ============ kernel 4: FUSED per-node pipeline ============
// grid 1152 (8*144), block 256, 64 nodes/block
__global__ void __launch_bounds__(256)
k_node(const float* __restrict__ sc,
       const float* __restrict__ gl_g, const float* __restrict__ gl_b,
       const float* __restrict__ nproj_w, const float* __restrict__ nproj_b,
       float* __restrict__ out)
{
    extern __shared__ float sm[];
    float* s_w    = sm;              // 16896
    float* s_node = s_w    + 16896;  // 8448
    float* s_Kp   = s_node + 8448;   // 2112
    float* s_H    = s_Kp   + 2112;
    float* s_V    = s_H    + 2112;
    float* s_Hw   = s_V    + 2112;
    float* s_Vw   = s_Hw   + 2112;
    float* s_gate = s_Vw   + 2112;   // 8448
    float* s_att  = s_gate + 8448;   // 1024
    float* s_sc   = s_att  + 1024;   // 1024
    float* s_GH   = s_sc   + 1024;   // 256
    float* s_GV   = s_GH   + 256;
    float* s_u    = s_GV   + 256;    // 128
    float* s_t    = s_u    + 128;
    float* s_hs   = s_t    + 128;    // 16
    float* s_vs   = s_hs   + 16;
    float* s_kb   = s_vs   + 16;
    float* s_m    = s_kb   + 16;     // 64
    float* s_rs   = s_m    + 64;

    int b  = blockIdx.x / 144;
    int n0 = (blockIdx.x % 144) * 64;
    int tid = threadIdx.x;

    // ---- stage ----
    for (int i4 = tid; i4 < 4096; i4 += 256){
        int r = i4 >> 5, k4 = i4 & 31;
        ((float4*)(s_w + r*132))[k4] = ((const float4*)nproj_w)[i4];
    }
    for (int i4 = tid; i4 < 2048; i4 += 256){
        int n = i4 >> 5, c4 = i4 & 31;
        ((float4*)(s_node + n*132))[c4] =
            ((const float4*)(g_node + (size_t)(b*NN + n0 + n)*CC))[c4];
    }
    for (int i4 = tid; i4 < 512; i4 += 256){
        int e = i4 >> 5, c4 = i4 & 31;
        ((float4*)(s_Kp + e*132))[c4] = ((const float4*)(g_Kp    + b*2048))[i4];
        ((float4*)(s_H  + e*132))[c4] = ((const float4*)(g_hyperF+ b*2048))[i4];
        ((float4*)(s_V  + e*132))[c4] = ((const float4*)(g_V     + b*2048))[i4];
        ((float4*)(s_Hw + e*132))[c4] = ((const float4*)(g_Hw    + b*2048))[i4];
        ((float4*)(s_Vw + e*132))[c4] = ((const float4*)(g_Vw    + b*2048))[i4];
    }
    {
        int i4 = tid;
        if (i4 < 256) ((float4*)s_sc)[i4] = ((const float4*)(sc + (size_t)(b*NN + n0)*16))[i4];
        if (i4 < 64){
            ((float4*)s_GH)[i4] = ((const float4*)(g_GH + b*256))[i4];
            ((float4*)s_GV)[i4] = ((const float4*)(g_GV + b*256))[i4];
        }
        if (i4 < 32){
            ((float4*)s_u)[i4] = ((const float4*)g_u)[i4];
            ((float4*)s_t)[i4] = ((const float4*)g_t)[i4];
        }
        if (i4 < 16){ s_hs[i4]=g_hs[b*16+i4]; s_vs[i4]=g_vs[b*16+i4]; s_kb[i4]=g_kb[b*16+i4]; }
    }
    __syncthreads();

    // ---- logits: att_pre[n,e] = node[n].Kp[e] + kb[e] ----
    {
        int n = tid >> 2, q = tid & 3;
        const float4* nr = (const float4*)(s_node + n*132);
        float acc[4] = {0.f,0.f,0.f,0.f};
        const float4* kp0 = (const float4*)(s_Kp + (q*4+0)*132);
        const float4* kp1 = (const float4*)(s_Kp + (q*4+1)*132);
        const float4* kp2 = (const float4*)(s_Kp + (q*4+2)*132);
        const float4* kp3 = (const float4*)(s_Kp + (q*4+3)*132);
        #pragma unroll 8
        for (int kk = 0; kk < 32; kk++){
            float4 a = nr[kk];
            float4 k0 = kp0[kk], k1 = kp1[kk], k2 = kp2[kk], k3 = kp3[kk];
            acc[0] += a.x*k0.x + a.y*k0.y + a.z*k0.z + a.w*k0.w;
            acc[1] += a.x*k1.x + a.y*k1.y + a.z*k1.z + a.w*k1.w;
            acc[2] += a.x*k2.x + a.y*k2.y + a.z*k2.z + a.w*k2.w;
            acc[3] += a.x*k3.x + a.y*k3.y + a.z*k3.z + a.w*k3.w;
        }
        #pragma unroll
        for (int i=0;i<4;i++) s_att[n*16 + q*4 + i] = acc[i] + s_kb[q*4+i];
    }
    __syncthreads();

    // ---- softmax + LN256 statistics via Gram matrices (one thread per node) ----
    if (tid < 64){
        int n = tid;
        float scv[16], atv[16];
        float* row = s_att + n*16;
        float mx = row[0];
        #pragma unroll
        for (int e=1;e<16;e++) mx = fmaxf(mx, row[e]);
        float s = 0.f;
        #pragma unroll
        for (int e=0;e<16;e++){ float v = expf(row[e]-mx); atv[e]=v; s+=v; }
        float inv = 1.f/s;
        #pragma unroll
        for (int e=0;e<16;e++){ atv[e] *= inv; row[e] = atv[e]; scv[e] = s_sc[n*16+e]; }
        float mean = 0.f;
        #pragma unroll
        for (int e=0;e<16;e++) mean += scv[e]*s_hs[e] + atv[e]*s_vs[e];
        mean *= (1.f/256.f);
        float ssq = 0.f;
        #pragma unroll
        for (int e=0;e<16;e++){
            float t1 = 0.f, t2 = 0.f;
            #pragma unroll
            for (int f=0;f<16;f++){
                t1 += scv[f]*s_GH[e*16+f];
                t2 += atv[f]*s_GV[e*16+f];
            }
            ssq += scv[e]*t1 + atv[e]*t2;
        }
        float var = ssq*(1.f/256.f) - mean*mean;
        s_m[n] = mean;
        s_rs[n] = rsqrtf(var + 1e-5f);
    }
    __syncthreads();

    // ---- gate linear via rank-16: gp[n,j] = rs*(S - m*u_j) + t_j ----
    {
        int j = tid & 127, g = tid >> 7;
        float uj = s_u[j], tj = s_t[j];
        for (int blk = 0; blk < 4; blk++){
            int nb = g*32 + blk*8;
            float acc[8] = {0,0,0,0,0,0,0,0};
            #pragma unroll
            for (int kk = 0; kk < 4; kk++){
                float b0 = s_Hw[(kk*4+0)*132 + j];
                float b1 = s_Hw[(kk*4+1)*132 + j];
                float b2 = s_Hw[(kk*4+2)*132 + j];
                float b3 = s_Hw[(kk*4+3)*132 + j];
                #pragma unroll
                for (int i=0;i<8;i++){
                    float4 a = ((const float4*)(s_sc + (nb+i)*16))[kk];
                    acc[i] += a.x*b0 + a.y*b1 + a.z*b2 + a.w*b3;
                }
            }
            #pragma unroll
            for (int kk = 0; kk < 4; kk++){
                float b0 = s_Vw[(kk*4+0)*132 + j];
                float b1 = s_Vw[(kk*4+1)*132 + j];
                float b2 = s_Vw[(kk*4+2)*132 + j];
                float b3 = s_Vw[(kk*4+3)*132 + j];
                #pragma unroll
                for (int i=0;i<8;i++){
                    float4 a = ((const float4*)(s_att + (nb+i)*16))[kk];
                    acc[i] += a.x*b0 + a.y*b1 + a.z*b2 + a.w*b3;
                }
            }
            #pragma unroll
            for (int i=0;i<8;i++){
                int n = nb + i;
                s_gate[n*132 + j] = s_rs[n]*(acc[i] - s_m[n]*uj) + tj;
            }
        }
    }
    __syncthreads();

    // ---- LN128 + sigmoid on gate rows ----
    {
        int w = tid >> 5, lane = tid & 31;
        float g0 = gl_g[lane], g1 = gl_g[lane+32], g2 = gl_g[lane+64], g3 = gl_g[lane+96];
        float b0 = gl_b[lane], b1 = gl_b[lane+32], b2 = gl_b[lane+64], b3 = gl_b[lane+96];
        for (int r = w*8; r < w*8 + 8; r++){
            float v0 = s_gate[r*132+lane],    v1 = s_gate[r*132+lane+32];
            float v2 = s_gate[r*132+lane+64], v3 = s_gate[r*132+lane+96];
            float s = v0+v1+v2+v3;
            for (int o=16;o;o>>=1) s += __shfl_xor_sync(0xffffffffu, s, o);
            float m = s*(1.f/128.f);
            float d0=v0-m, d1=v1-m, d2=v2-m, d3=v3-m;
            float q = d0*d0+d1*d1+d2*d2+d3*d3;
            for (int o=16;o;o>>=1) q += __shfl_xor_sync(0xffffffffu, q, o);
            float rs = rsqrtf(q*(1.f/128.f)+1e-5f);
            s_gate[r*132+lane]    = 1.f/(1.f+expf(-(d0*rs*g0+b0)));
            s_gate[r*132+lane+32] = 1.f/(1.f+expf(-(d1*rs*g1+b1)));
            s_gate[r*132+lane+64] = 1.f/(1.f+expf(-(d2*rs*g2+b2)));
            s_gate[r*132+lane+96] = 1.f/(1.f+expf(-(d3*rs*g3+b3)));
        }
    }
    __syncthreads();

    // ---- upd = node + g*intra + (1-g)*cross  (in place into s_node) ----
    {
        int c = tid & 127, g = tid >> 7;
        float hcol[16], vcol[16];
        #pragma unroll
        for (int e=0;e<16;e++){ hcol[e] = s_H[e*132+c]; vcol[e] = s_V[e*132+c]; }
        for (int n = g*32; n < g*32 + 32; n++){
            float intra = 0.f, cross = 0.f;
            #pragma unroll
            for (int kk=0; kk<4; kk++){
                float4 a = ((const float4*)(s_sc  + n*16))[kk];
                float4 t = ((const float4*)(s_att + n*16))[kk];
                intra += a.x*hcol[kk*4] + a.y*hcol[kk*4+1] + a.z*hcol[kk*4+2] + a.w*hcol[kk*4+3];
                cross += t.x*vcol[kk*4] + t.y*vcol[kk*4+1] + t.z*vcol[kk*4+2] + t.w*vcol[kk*4+3];
            }
            float gt = s_gate[n*132+c];
            s_node[n*132+c] = s_node[n*132+c] + gt*intra + (1.f-gt)*cross;
        }
    }
    __syncthreads();

    // ---- nproj GEMM + gelu + direct transposed store ----
    {
        int j = tid & 31, g = tid >> 5;
        int nb = g*8;
        float acc[4][8];
        #pragma unroll
        for (int cc=0;cc<4;cc++){
            float bias = nproj_b[j + 32*cc];
            #pragma unroll
            for (int i=0;i<8;i++) acc[cc][i] = bias;
        }
        const float4* w0 = (const float4*)(s_w + (j     )*132);
        const float4* w1 = (const float4*)(s_w + (j + 32)*132);
        const float4* w2 = (const float4*)(s_w + (j + 64)*132);
        const float4* w3 = (const float4*)(s_w + (j + 96)*132);
        #pragma unroll 4
        for (int kk = 0; kk < 32; kk++){
            float4 a[8];
            #pragma unroll
            for (int i=0;i<8;i++) a[i] = ((const float4*)(s_node + (nb+i)*132))[kk];
            float4 wv0 = w0[kk], wv1 = w1[kk], wv2 = w2[kk], wv3 = w3[kk];
            #pragma unroll
            for (int i=0;i<8;i++){
                acc[0][i] += a[i].x*wv0.x + a[i].y*wv0.y + a[i].z*wv0.z + a[i].w*wv0.w;
                acc[1][i] += a[i].x*wv1.x + a[i].y*wv1.y + a[i].z*wv1.z + a[i].w*wv1.w;
                acc[2][i] += a[i].x*wv2.x + a[i].y*wv2.y + a[i].z*wv2.z + a[i].w*wv2.w;
                acc[3][i] += a[i].x*wv3.x + a[i].y*wv3.y + a[i].z*wv3.z + a[i].w*wv3.w;
            }
        }
        #pragma unroll
        for (int cc=0;cc<4;cc++){
            int c = j + 32*cc;
            float4 o1, o2;
            o1.x = gelu_exact(acc[cc][0]); o1.y = gelu_exact(acc[cc][1]);
            o1.z = gelu_exact(acc[cc][2]); o1.w = gelu_exact(acc[cc][3]);
            o2.x = gelu_exact(acc[cc][4]); o2.y = gelu_exact(acc[cc][5]);
            o2.z = gelu_exact(acc[cc][6]); o2.w = gelu_exact(acc[cc][7]);
            float* dst = out + (size_t)(b*CC + c)*NN + n0 + nb;
            ((float4*)dst)[0] = o1;
            ((float4*)dst)[1] = o2;
        }
    }
}

// ---------------- launch ----------------
extern "C" void kernel_launch(void* const* d_in, const int* in_sizes, int n_in,
                              void* d_out, int out_size)
{
    const float* fm        = (const float*)d_in[0];
    const float* sc        = (const float*)d_in[1];
    const float* np_g      = (const float*)d_in[2];
    const float* np_b      = (const float*)d_in[3];
    const float* mha_w_in  = (const float*)d_in[4];
    const float* mha_b_in  = (const float*)d_in[5];
    const float* mha_w_out = (const float*)d_in[6];
    const float* mha_b_out = (const float*)d_in[7];
    const float* ffn_w1    = (const float*)d_in[8];
    const float* ffn_b1    = (const float*)d_in[9];
    const float* ffn_w2    = (const float*)d_in[10];
    const float* ffn_b2    = (const float*)d_in[11];
    const float* tnorm_g   = (const float*)d_in[12];
    const float* tnorm_b   = (const float*)d_in[13];
    const float* nh_g      = (const float*)d_in[14];
    const float* nh_b      = (const float*)d_in[15];
    const float* hp_w      = (const float*)d_in[16];
    const float* hp_b      = (const float*)d_in[17];
    const float* q_w       = (const float*)d_in[18];
    const float* q_b       = (const float*)d_in[19];
    const float* kv_w      = (const float*)d_in[20];
    const float* kv_b      = (const float*)d_in[21];
    const float* nf_g      = (const float*)d_in[22];
    const float* nf_b      = (const float*)d_in[23];
    const float* gate_w    = (const float*)d_in[24];
    const float* gate_b    = (const float*)d_in[25];
    const float* gl_g      = (const float*)d_in[26];
    const float* gl_b      = (const float*)d_in[27];
    const float* nproj_w   = (const float*)d_in[28];
    const float* nproj_b   = (const float*)d_in[29];

    const int smem_hyper = (2112*4 + 4224 + 1024 + 33792) * 4;   // 189952
    const int smem_node  = 47344 * 4;                            // 189376

    cudaFuncSetAttribute(k_hyper, cudaFuncAttributeMaxDynamicSharedMemorySize, smem_hyper);
    cudaFuncSetAttribute(k_node,  cudaFuncAttributeMaxDynamicSharedMemorySize, smem_node);

    k_node_ln<<<2304, 128>>>(fm, np_g, np_b, sc);
    k_reduce<<<128, 128>>>();
    k_hyper<<<8, 512, smem_hyper>>>(mha_w_in, mha_b_in, mha_w_out, mha_b_out,
                                    ffn_w1, ffn_b1, ffn_w2, ffn_b2,
                                    tnorm_g, tnorm_b, nh_g, nh_b,
                                    hp_w, hp_b, kv_w, kv_b, q_w, q_b,
                                    gate_w, gate_b, nf_g, nf_b);
    k_node<<<1152, 256, smem_node>>>(sc, gl_g, gl_b, nproj_w, nproj_b, (float*)d_out);
}

// round 5
// speedup vs baseline: 3.9482x; 1.1509x over previous
#include <cuda_runtime.h>
#include <math.h>

#define BB 8
#define CC 128
#define NN 9216
#define EE 16

// ---------------- scratch ----------------
__device__ float g_node [BB*NN*CC];
__device__ float g_part [BB*72*EE*CC];
__device__ float g_hyper [BB*EE*CC];
__device__ float g_hyperF[BB*EE*CC];
__device__ float g_V [BB*EE*CC];
__device__ float g_Kp[BB*EE*CC];
__device__ float g_kb[BB*EE];
__device__ float g_Hw[BB*EE*CC];
__device__ float g_Vw[BB*EE*CC];
__device__ float g_GH[BB*EE*EE];
__device__ float g_GV[BB*EE*EE];
__device__ float g_hs[BB*EE];
__device__ float g_vs[BB*EE];
__device__ float g_u[CC];
__device__ float g_t[CC];

__device__ __forceinline__ float gelu_exact(float x){
    return 0.5f*x*(1.0f + erff(x*0.70710678118654752f));
}

// ============ kernel 1: transpose + LayerNorm(node) + agg partials ============
// grid 576 (8*72), block 512, 128 nodes/block
__global__ void __launch_bounds__(512)
k_node_ln(const float* __restrict__ fm,
          const float* __restrict__ gam,
          const float* __restrict__ bet,
          const float* __restrict__ sc)
{
    extern __shared__ float sm[];
    float* tile   = sm;              // 128*132
    float* s_sc   = tile + 16896;    // 2048
    float* s_part = s_sc + 2048;     // 8192
    float* s_mean = s_part + 8192;   // 128
    float* s_rstd = s_mean + 128;    // 128
    int b  = blockIdx.x / 72;
    int n0 = (blockIdx.x % 72) * 128;
    int tid = threadIdx.x;

    for (int i = tid; i < 16384; i += 512){
        int c = i >> 7, n = i & 127;
        tile[n*132 + c] = fm[(size_t)(b*CC + c)*NN + n0 + n];
    }
    for (int i = tid; i < 2048; i += 512)
        s_sc[i] = sc[(size_t)(b*NN + n0)*EE + i];
    __syncthreads();

    int w = tid >> 5, lane = tid & 31;
    for (int n = w*8; n < w*8 + 8; n++){
        float v0 = tile[n*132+lane],    v1 = tile[n*132+lane+32];
        float v2 = tile[n*132+lane+64], v3 = tile[n*132+lane+96];
        float s = v0+v1+v2+v3;
        for (int o=16;o;o>>=1) s += __shfl_xor_sync(0xffffffffu, s, o);
        float m = s * (1.0f/128.0f);
        float d0=v0-m, d1=v1-m, d2=v2-m, d3=v3-m;
        float q = d0*d0+d1*d1+d2*d2+d3*d3;
        for (int o=16;o;o>>=1) q += __shfl_xor_sync(0xffffffffu, q, o);
        if (lane == 0){ s_mean[n]=m; s_rstd[n]=rsqrtf(q*(1.0f/128.0f)+1e-5f); }
    }
    __syncthreads();

    int c = tid & 127, q = tid >> 7;     // q in 0..3, 32 nodes each
    float gg = gam[c], bb = bet[c];
    float acc[16];
    #pragma unroll
    for (int e=0;e<16;e++) acc[e]=0.f;
    for (int n = q*32; n < q*32 + 32; n++){
        float v = (tile[n*132+c]-s_mean[n])*s_rstd[n]*gg + bb;
        g_node[(size_t)(b*NN + n0 + n)*CC + c] = v;
        #pragma unroll
        for (int e=0;e<16;e++) acc[e] += s_sc[n*16+e]*v;
    }
    #pragma unroll
    for (int e=0;e<16;e++) s_part[q*2048 + e*128 + c] = acc[e];
    __syncthreads();

    for (int i = tid; i < 2048; i += 512){
        float s = s_part[i] + s_part[2048+i] + s_part[4096+i] + s_part[6144+i];
        g_part[(size_t)(b*72 + (blockIdx.x%72))*2048 + i] = s;
    }
}

// ============ kernel 2: reduce agg partials ============
__global__ void k_reduce()
{
    int i = blockIdx.x*128 + threadIdx.x;   // 16384 total
    int b = i >> 11, rem = i & 2047;
    float s = 0.f;
    #pragma unroll 4
    for (int j = 0; j < 72; j++) s += g_part[(size_t)(b*72 + j)*2048 + rem];
    g_hyper[b*2048 + rem] = s;
}

// ============ kernel 3: hyperedge transformer + per-batch precomputes ============
template<int CIN, int COUT, int ACT>
__device__ __forceinline__ void gemmF(const float* __restrict__ W,
                                      const float* __restrict__ bias,
                                      const float* in, int inPitch,
                                      float* out, int outPitch, float* sw)
{
    const int pitch = CIN + 4;
    const int cin4  = CIN >> 2;
    const float4* W4 = (const float4*)W;
    for (int i = threadIdx.x; i < (COUT*CIN)>>2; i += 512){
        int r = i / cin4, c4 = i - r*cin4;
        ((float4*)(sw + r*pitch))[c4] = W4[i];
    }
    __syncthreads();
    const int logC  = (COUT == 256) ? 8 : 7;
    const int estep = 512 >> logC;
    const int nE    = 16 / estep;
    int j  = threadIdx.x & (COUT-1);
    int e0 = threadIdx.x >> logC;
    const float4* wr = (const float4*)(sw + j*pitch);
    float acc[nE];
    const float4* ar[nE];
    #pragma unroll
    for (int r=0;r<nE;r++){ acc[r]=0.f; ar[r]=(const float4*)(in + (e0 + r*estep)*inPitch); }
    for (int kk = 0; kk < cin4; kk++){
        float4 wv = wr[kk];
        #pragma unroll
        for (int r=0;r<nE;r++){
            float4 av = ar[r][kk];
            acc[r] += av.x*wv.x + av.y*wv.y + av.z*wv.z + av.w*wv.w;
        }
    }
    float bj = bias[j];
    #pragma unroll
    for (int r=0;r<nE;r++){
        float v = acc[r] + bj;
        if (ACT) v = gelu_exact(v);
        out[(e0 + r*estep)*outPitch + j] = v;
    }
    __syncthreads();
}

__device__ __forceinline__ void ln16_128(const float* a, const float* r, int pitch,
                                         const float* __restrict__ g,
                                         const float* __restrict__ b,
                                         float* out, int outPitch)
{
    int w = threadIdx.x >> 5, lane = threadIdx.x & 31;
    if (w < 16){
        float v[4]; float s = 0.f;
        #pragma unroll
        for (int i=0;i<4;i++){
            float x = a[w*pitch + lane + 32*i];
            if (r) x += r[w*pitch + lane + 32*i];
            v[i] = x; s += x;
        }
        for (int o=16;o;o>>=1) s += __shfl_xor_sync(0xffffffffu, s, o);
        float m = s*(1.f/128.f), q = 0.f;
        #pragma unroll
        for (int i=0;i<4;i++){ float d=v[i]-m; q += d*d; }
        for (int o=16;o;o>>=1) q += __shfl_xor_sync(0xffffffffu, q, o);
        float rs = rsqrtf(q*(1.f/128.f)+1e-5f);
        #pragma unroll
        for (int i=0;i<4;i++)
            out[w*outPitch + lane + 32*i] = (v[i]-m)*rs*g[lane+32*i] + b[lane+32*i];
    }
    __syncthreads();
}

__global__ void __launch_bounds__(512)
k_hyper(const float* __restrict__ mha_w_in, const float* __restrict__ mha_b_in,
        const float* __restrict__ mha_w_out, const float* __restrict__ mha_b_out,
        const float* __restrict__ ffn_w1, const float* __restrict__ ffn_b1,
        const float* __restrict__ ffn_w2, const float* __restrict__ ffn_b2,
        const float* __restrict__ tnorm_g, const float* __restrict__ tnorm_b,
        const float* __restrict__ nh_g, const float* __restrict__ nh_b,
        const float* __restrict__ hp_w, const float* __restrict__ hp_b,
        const float* __restrict__ kv_w, const float* __restrict__ kv_b,
        const float* __restrict__ q_w, const float* __restrict__ q_b,
        const float* __restrict__ gate_w, const float* __restrict__ gate_b,
        const float* __restrict__ nf_g, const float* __restrict__ nf_b)
{
    extern __shared__ float sm[];
    float* s0   = sm;            // 16*132
    float* s1   = s0 + 2112;
    float* s2   = s1 + 2112;
    float* s3   = s2 + 2112;
    float* sh   = s3 + 2112;     // 16*264
    float* satt = sh + 4224;     // 1024
    float* sw   = satt + 1024;   // 33792 floats
    int b = blockIdx.x, tid = threadIdx.x;

    for (int i = tid; i < 2048; i += 512)
        s0[(i>>7)*132 + (i&127)] = g_hyper[b*2048 + i];
    __syncthreads();

    gemmF<128,128,0>(mha_w_in,           mha_b_in,     s0,132, s1,132, sw);
    gemmF<128,128,0>(mha_w_in + 128*128, mha_b_in+128, s0,132, s2,132, sw);
    gemmF<128,128,0>(mha_w_in + 256*128, mha_b_in+256, s0,132, s3,132, sw);

    for (int p = tid; p < 1024; p += 512){
        int h = p>>8, e1 = (p>>4)&15, e2 = p&15;
        const float* qr = s1 + e1*132 + h*32;
        const float* kr = s2 + e2*132 + h*32;
        float acc = 0.f;
        #pragma unroll
        for (int d=0; d<32; d++) acc += qr[d]*kr[d];
        satt[p] = acc * 0.17677669529663687f;
    }
    __syncthreads();
    if (tid < 64){
        float* row = satt + tid*16;
        float mx = row[0];
        #pragma unroll
        for (int e=1;e<16;e++) mx = fmaxf(mx, row[e]);
        float s = 0.f;
        #pragma unroll
        for (int e=0;e<16;e++){ float v = expf(row[e]-mx); row[e]=v; s+=v; }
        float inv = 1.f/s;
        #pragma unroll
        for (int e=0;e<16;e++) row[e] *= inv;
    }
    __syncthreads();
    for (int p = tid; p < 2048; p += 512){
        int e = p>>7, c = p&127, h = c>>5;
        float acc = 0.f;
        #pragma unroll
        for (int e2=0;e2<16;e2++) acc += satt[(h*16+e)*16 + e2] * s3[e2*132 + c];
        s1[e*132 + c] = acc;
    }
    __syncthreads();
    gemmF<128,128,0>(mha_w_out, mha_b_out, s1,132, s2,132, sw);
    ln16_128(s0, s2, 132, tnorm_g, tnorm_b, s3, 132);
    gemmF<128,256,1>(ffn_w1, ffn_b1, s3,132, sh,264, sw);
    gemmF<256,128,0>(ffn_w2, ffn_b2, sh,264, s1,132, sw);
    ln16_128(s3, s1, 132, tnorm_g, tnorm_b, s2, 132);
    ln16_128(s2, (const float*)0, 132, nh_g, nh_b, s3, 132);
    gemmF<128,128,1>(hp_w, hp_b, s3,132, s0,132, sw);               // H -> s0
    gemmF<128,128,0>(kv_w,           kv_b,     s0,132, s1,132, sw); // K -> s1
    gemmF<128,128,0>(kv_w + 128*128, kv_b+128, s0,132, s2,132, sw); // V -> s2

    // Kp[e,c] (pre-scaled) and kb[e]
    {
        const float4* W4 = (const float4*)q_w;
        for (int i = tid; i < 4096; i += 512){
            int r = i >> 5, c4 = i & 31;
            ((float4*)(sw + r*132))[c4] = W4[i];
        }
        __syncthreads();
        const float scl = 0.08838834764831845f;
        for (int o = tid; o < 2048; o += 512){
            int e = o>>7, k = o&127;
            float acc = 0.f;
            for (int c = 0; c < 128; c++) acc += s1[e*132+c]*sw[c*132+k];
            g_Kp[b*2048 + o] = acc * scl;
        }
        if (tid < 16){
            float acc = 0.f;
            for (int c = 0; c < 128; c++) acc += q_b[c]*s1[tid*132+c];
            g_kb[b*16 + tid] = acc * scl;
        }
    }
    __syncthreads();

    // gate decomposition precomputes
    {
        const float4* GW4 = (const float4*)gate_w;
        for (int i = tid; i < 8192; i += 512){
            int r = i >> 6, c4 = i & 63;
            ((float4*)(sw + r*264))[c4] = GW4[i];
        }
        __syncthreads();
        if (tid < 128){
            float t = gate_b[tid];
            for (int c = 0; c < 256; c++) t += nf_b[c]*sw[tid*264+c];
            g_t[tid] = t;
        }
        __syncthreads();
        for (int i = tid; i < 32768; i += 512){
            int r = i >> 8, c = i & 255;
            sw[r*264+c] *= nf_g[c];
        }
        __syncthreads();
        if (tid < 128){
            float u = 0.f;
            for (int c = 0; c < 256; c++) u += sw[tid*264+c];
            g_u[tid] = u;
        }
        for (int p = tid; p < 2048; p += 512){
            int j = p & 127, e = p >> 7;
            const float4* hr = (const float4*)(s0 + e*132);
            const float4* vr = (const float4*)(s2 + e*132);
            const float4* w1 = (const float4*)(sw + j*264);
            const float4* w2 = (const float4*)(sw + j*264 + 128);
            float a1 = 0.f, a2 = 0.f;
            #pragma unroll 8
            for (int kk = 0; kk < 32; kk++){
                float4 h = hr[kk], w = w1[kk];
                a1 += h.x*w.x + h.y*w.y + h.z*w.z + h.w*w.w;
                float4 v = vr[kk], x = w2[kk];
                a2 += v.x*x.x + v.y*x.y + v.z*x.z + v.w*x.w;
            }
            g_Hw[b*2048+p] = a1; g_Vw[b*2048+p] = a2;
        }
        if (tid < 512){
            int q = tid;
            const float* A = (q < 256) ? s0 : s2;
            int qq = q & 255;
            int e = qq >> 4, f = qq & 15;
            const float4* r1 = (const float4*)(A + e*132);
            const float4* r2 = (const float4*)(A + f*132);
            float acc = 0.f;
            #pragma unroll 8
            for (int kk = 0; kk < 32; kk++){
                float4 a = r1[kk], c = r2[kk];
                acc += a.x*c.x + a.y*c.y + a.z*c.z + a.w*c.w;
            }
            if (q < 256) g_GH[b*256+qq] = acc; else g_GV[b*256+qq] = acc;
        }
        if (tid < 32){
            int e = tid & 15;
            const float* A = (tid < 16) ? s0 : s2;
            float s = 0.f;
            for (int c = 0; c < 128; c++) s += A[e*132+c];
            if (tid < 16) g_hs[b*16+e] = s; else g_vs[b*16+e] = s;
        }
    }

    for (int i = tid; i < 2048; i += 512){
        int e = i>>7, c = i&127, o = b*2048 + i;
        g_hyperF[o] = s0[e*132+c];
        g_V[o]      = s2[e*132+c];
    }
}

// ============ kernel 4: FUSED per-node pipeline ============
// grid 576 (8*72), block 512, 128 nodes/block
// smem overlay: gate buffer and nproj weight buffer share one 16896-float region.
__global__ void __launch_bounds__(512)
k_node(const float* __restrict__ sc,
       const float* __restrict__ gl_g, const float* __restrict__ gl_b,
       const float* __restrict__ nproj_w, const float* __restrict__ nproj_b,
       float* __restrict__ out)
{
    extern __shared__ float sm[];
    float* s_node = sm;              // 16896 (128*132)
    float* s_ov   = s_node + 16896;  // 16896 overlay: gate, then nproj weights
    float* s_Kp   = s_ov   + 16896;  // 2112
    float* s_H    = s_Kp   + 2112;
    float* s_V    = s_H    + 2112;
    float* s_Hw   = s_V    + 2112;
    float* s_Vw   = s_Hw   + 2112;
    float* s_att  = s_Vw   + 2112;   // 2048 (128*16)
    float* s_sc   = s_att  + 2048;   // 2048
    float* s_GH   = s_sc   + 2048;   // 256
    float* s_GV   = s_GH   + 256;
    float* s_u    = s_GV   + 256;    // 128
    float* s_t    = s_u    + 128;
    float* s_m    = s_t    + 128;    // 128
    float* s_rs   = s_m    + 128;
    float* s_hs   = s_rs   + 128;    // 16
    float* s_vs   = s_hs   + 16;
    float* s_kb   = s_vs   + 16;

    int b  = blockIdx.x / 72;
    int n0 = (blockIdx.x % 72) * 128;
    int tid = threadIdx.x;

    // ---- stage (not s_ov) ----
    for (int i4 = tid; i4 < 4096; i4 += 512){
        int n = i4 >> 5, c4 = i4 & 31;
        ((float4*)(s_node + n*132))[c4] =
            ((const float4*)(g_node + (size_t)(b*NN + n0 + n)*CC))[c4];
    }
    {
        int i4 = tid;
        if (i4 < 512){
            int e = i4 >> 5, c4 = i4 & 31;
            ((float4*)(s_Kp + e*132))[c4] = ((const float4*)(g_Kp    + b*2048))[i4];
            ((float4*)(s_H  + e*132))[c4] = ((const float4*)(g_hyperF+ b*2048))[i4];
            ((float4*)(s_V  + e*132))[c4] = ((const float4*)(g_V     + b*2048))[i4];
            ((float4*)(s_Hw + e*132))[c4] = ((const float4*)(g_Hw    + b*2048))[i4];
            ((float4*)(s_Vw + e*132))[c4] = ((const float4*)(g_Vw    + b*2048))[i4];
        }
        if (i4 < 512) ((float4*)s_sc)[i4] = ((const float4*)(sc + (size_t)(b*NN + n0)*16))[i4];
        if (i4 < 64){
            ((float4*)s_GH)[i4] = ((const float4*)(g_GH + b*256))[i4];
            ((float4*)s_GV)[i4] = ((const float4*)(g_GV + b*256))[i4];
        }
        if (i4 < 32){
            ((float4*)s_u)[i4] = ((const float4*)g_u)[i4];
            ((float4*)s_t)[i4] = ((const float4*)g_t)[i4];
        }
        if (i4 < 16){ s_hs[i4]=g_hs[b*16+i4]; s_vs[i4]=g_vs[b*16+i4]; s_kb[i4]=g_kb[b*16+i4]; }
    }
    __syncthreads();

    // ---- logits: att_pre[n,e] = node[n].Kp[e] + kb[e] (512 thr, n=tid>>2) ----
    {
        int n = tid >> 2, q = tid & 3;
        const float4* nr = (const float4*)(s_node + n*132);
        float acc[4] = {0.f,0.f,0.f,0.f};
        const float4* kp0 = (const float4*)(s_Kp + (q*4+0)*132);
        const float4* kp1 = (const float4*)(s_Kp + (q*4+1)*132);
        const float4* kp2 = (const float4*)(s_Kp + (q*4+2)*132);
        const float4* kp3 = (const float4*)(s_Kp + (q*4+3)*132);
        #pragma unroll 8
        for (int kk = 0; kk < 32; kk++){
            float4 a = nr[kk];
            float4 k0 = kp0[kk], k1 = kp1[kk], k2 = kp2[kk], k3 = kp3[kk];
            acc[0] += a.x*k0.x + a.y*k0.y + a.z*k0.z + a.w*k0.w;
            acc[1] += a.x*k1.x + a.y*k1.y + a.z*k1.z + a.w*k1.w;
            acc[2] += a.x*k2.x + a.y*k2.y + a.z*k2.z + a.w*k2.w;
            acc[3] += a.x*k3.x + a.y*k3.y + a.z*k3.z + a.w*k3.w;
        }
        #pragma unroll
        for (int i=0;i<4;i++) s_att[n*16 + q*4 + i] = acc[i] + s_kb[q*4+i];
    }
    __syncthreads();

    // ---- softmax + LN256 stats via Gram matrices (one thread per node) ----
    if (tid < 128){
        int n = tid;
        float scv[16], atv[16];
        float* row = s_att + n*16;
        float mx = row[0];
        #pragma unroll
        for (int e=1;e<16;e++) mx = fmaxf(mx, row[e]);
        float s = 0.f;
        #pragma unroll
        for (int e=0;e<16;e++){ float v = expf(row[e]-mx); atv[e]=v; s+=v; }
        float inv = 1.f/s;
        #pragma unroll
        for (int e=0;e<16;e++){ atv[e] *= inv; row[e] = atv[e]; scv[e] = s_sc[n*16+e]; }
        float mean = 0.f;
        #pragma unroll
        for (int e=0;e<16;e++) mean += scv[e]*s_hs[e] + atv[e]*s_vs[e];
        mean *= (1.f/256.f);
        float ssq = 0.f;
        #pragma unroll
        for (int e=0;e<16;e++){
            float t1 = 0.f, t2 = 0.f;
            #pragma unroll
            for (int f=0;f<16;f++){
                t1 += scv[f]*s_GH[e*16+f];
                t2 += atv[f]*s_GV[e*16+f];
            }
            ssq += scv[e]*t1 + atv[e]*t2;
        }
        float var = ssq*(1.f/256.f) - mean*mean;
        s_m[n] = mean;
        s_rs[n] = rsqrtf(var + 1e-5f);
    }
    __syncthreads();

    // ---- gate linear via rank-16 into overlay ----
    {
        float* s_gate = s_ov;
        int j = tid & 127, g = tid >> 7;      // g in 0..3 -> 32 nodes each
        float uj = s_u[j], tj = s_t[j];
        for (int blk = 0; blk < 4; blk++){
            int nb = g*32 + blk*8;
            float acc[8] = {0,0,0,0,0,0,0,0};
            #pragma unroll
            for (int kk = 0; kk < 4; kk++){
                float b0 = s_Hw[(kk*4+0)*132 + j];
                float b1 = s_Hw[(kk*4+1)*132 + j];
                float b2 = s_Hw[(kk*4+2)*132 + j];
                float b3 = s_Hw[(kk*4+3)*132 + j];
                #pragma unroll
                for (int i=0;i<8;i++){
                    float4 a = ((const float4*)(s_sc + (nb+i)*16))[kk];
                    acc[i] += a.x*b0 + a.y*b1 + a.z*b2 + a.w*b3;
                }
            }
            #pragma unroll
            for (int kk = 0; kk < 4; kk++){
                float b0 = s_Vw[(kk*4+0)*132 + j];
                float b1 = s_Vw[(kk*4+1)*132 + j];
                float b2 = s_Vw[(kk*4+2)*132 + j];
                float b3 = s_Vw[(kk*4+3)*132 + j];
                #pragma unroll
                for (int i=0;i<8;i++){
                    float4 a = ((const float4*)(s_att + (nb+i)*16))[kk];
                    acc[i] += a.x*b0 + a.y*b1 + a.z*b2 + a.w*b3;
                }
            }
            #pragma unroll
            for (int i=0;i<8;i++){
                int n = nb + i;
                s_gate[n*132 + j] = s_rs[n]*(acc[i] - s_m[n]*uj) + tj;
            }
        }
    }
    __syncthreads();

    // ---- LN128 + sigmoid on gate rows (16 warps x 8 rows) ----
    {
        float* s_gate = s_ov;
        int w = tid >> 5, lane = tid & 31;
        float g0 = gl_g[lane], g1 = gl_g[lane+32], g2 = gl_g[lane+64], g3 = gl_g[lane+96];
        float b0 = gl_b[lane], b1 = gl_b[lane+32], b2 = gl_b[lane+64], b3 = gl_b[lane+96];
        for (int r = w*8; r < w*8 + 8; r++){
            float v0 = s_gate[r*132+lane],    v1 = s_gate[r*132+lane+32];
            float v2 = s_gate[r*132+lane+64], v3 = s_gate[r*132+lane+96];
            float s = v0+v1+v2+v3;
            for (int o=16;o;o>>=1) s += __shfl_xor_sync(0xffffffffu, s, o);
            float m = s*(1.f/128.f);
            float d0=v0-m, d1=v1-m, d2=v2-m, d3=v3-m;
            float q = d0*d0+d1*d1+d2*d2+d3*d3;
            for (int o=16;o;o>>=1) q += __shfl_xor_sync(0xffffffffu, q, o);
            float rs = rsqrtf(q*(1.f/128.f)+1e-5f);
            s_gate[r*132+lane]    = 1.f/(1.f+expf(-(d0*rs*g0+b0)));
            s_gate[r*132+lane+32] = 1.f/(1.f+expf(-(d1*rs*g1+b1)));
            s_gate[r*132+lane+64] = 1.f/(1.f+expf(-(d2*rs*g2+b2)));
            s_gate[r*132+lane+96] = 1.f/(1.f+expf(-(d3*rs*g3+b3)));
        }
    }
    __syncthreads();

    // ---- upd = node + g*intra + (1-g)*cross (in place into s_node) ----
    {
        float* s_gate = s_ov;
        int c = tid & 127, g = tid >> 7;    // g in 0..3 -> 32 nodes each
        float hcol[16], vcol[16];
        #pragma unroll
        for (int e=0;e<16;e++){ hcol[e] = s_H[e*132+c]; vcol[e] = s_V[e*132+c]; }
        for (int n = g*32; n < g*32 + 32; n++){
            float intra = 0.f, cross = 0.f;
            #pragma unroll
            for (int kk=0; kk<4; kk++){
                float4 a = ((const float4*)(s_sc  + n*16))[kk];
                float4 t = ((const float4*)(s_att + n*16))[kk];
                intra += a.x*hcol[kk*4] + a.y*hcol[kk*4+1] + a.z*hcol[kk*4+2] + a.w*hcol[kk*4+3];
                cross += t.x*vcol[kk*4] + t.y*vcol[kk*4+1] + t.z*vcol[kk*4+2] + t.w*vcol[kk*4+3];
            }
            float gt = s_gate[n*132+c];
            s_node[n*132+c] = s_node[n*132+c] + gt*intra + (1.f-gt)*cross;
        }
    }
    __syncthreads();

    // ---- stage nproj weights into overlay (gate dead now) ----
    for (int i4 = tid; i4 < 4096; i4 += 512){
        int r = i4 >> 5, k4 = i4 & 31;
        ((float4*)(s_ov + r*132))[k4] = ((const float4*)nproj_w)[i4];
    }
    __syncthreads();

    // ---- nproj GEMM + gelu + direct transposed store ----
    {
        float* s_w = s_ov;
        int j = tid & 31, g = tid >> 5;     // g in 0..15 -> 8 nodes each
        int nb = g*8;
        float acc[4][8];
        #pragma unroll
        for (int cc=0;cc<4;cc++){
            float bias = nproj_b[j + 32*cc];
            #pragma unroll
            for (int i=0;i<8;i++) acc[cc][i] = bias;
        }
        const float4* w0 = (const float4*)(s_w + (j     )*132);
        const float4* w1 = (const float4*)(s_w + (j + 32)*132);
        const float4* w2 = (const float4*)(s_w + (j + 64)*132);
        const float4* w3 = (const float4*)(s_w + (j + 96)*132);
        #pragma unroll 4
        for (int kk = 0; kk < 32; kk++){
            float4 a[8];
            #pragma unroll
            for (int i=0;i<8;i++) a[i] = ((const float4*)(s_node + (nb+i)*132))[kk];
            float4 wv0 = w0[kk], wv1 = w1[kk], wv2 = w2[kk], wv3 = w3[kk];
            #pragma unroll
            for (int i=0;i<8;i++){
                acc[0][i] += a[i].x*wv0.x + a[i].y*wv0.y + a[i].z*wv0.z + a[i].w*wv0.w;
                acc[1][i] += a[i].x*wv1.x + a[i].y*wv1.y + a[i].z*wv1.z + a[i].w*wv1.w;
                acc[2][i] += a[i].x*wv2.x + a[i].y*wv2.y + a[i].z*wv2.z + a[i].w*wv2.w;
                acc[3][i] += a[i].x*wv3.x + a[i].y*wv3.y + a[i].z*wv3.z + a[i].w*wv3.w;
            }
        }
        #pragma unroll
        for (int cc=0;cc<4;cc++){
            int c = j + 32*cc;
            float4 o1, o2;
            o1.x = gelu_exact(acc[cc][0]); o1.y = gelu_exact(acc[cc][1]);
            o1.z = gelu_exact(acc[cc][2]); o1.w = gelu_exact(acc[cc][3]);
            o2.x = gelu_exact(acc[cc][4]); o2.y = gelu_exact(acc[cc][5]);
            o2.z = gelu_exact(acc[cc][6]); o2.w = gelu_exact(acc[cc][7]);
            float* dst = out + (size_t)(b*CC + c)*NN + n0 + nb;
            ((float4*)dst)[0] = o1;
            ((float4*)dst)[1] = o2;
        }
    }
}

// ---------------- launch ----------------
extern "C" void kernel_launch(void* const* d_in, const int* in_sizes, int n_in,
                              void* d_out, int out_size)
{
    const float* fm        = (const float*)d_in[0];
    const float* sc        = (const float*)d_in[1];
    const float* np_g      = (const float*)d_in[2];
    const float* np_b      = (const float*)d_in[3];
    const float* mha_w_in  = (const float*)d_in[4];
    const float* mha_b_in  = (const float*)d_in[5];
    const float* mha_w_out = (const float*)d_in[6];
    const float* mha_b_out = (const float*)d_in[7];
    const float* ffn_w1    = (const float*)d_in[8];
    const float* ffn_b1    = (const float*)d_in[9];
    const float* ffn_w2    = (const float*)d_in[10];
    const float* ffn_b2    = (const float*)d_in[11];
    const float* tnorm_g   = (const float*)d_in[12];
    const float* tnorm_b   = (const float*)d_in[13];
    const float* nh_g      = (const float*)d_in[14];
    const float* nh_b      = (const float*)d_in[15];
    const float* hp_w      = (const float*)d_in[16];
    const float* hp_b      = (const float*)d_in[17];
    const float* q_w       = (const float*)d_in[18];
    const float* q_b       = (const float*)d_in[19];
    const float* kv_w      = (const float*)d_in[20];
    const float* kv_b      = (const float*)d_in[21];
    const float* nf_g      = (const float*)d_in[22];
    const float* nf_b      = (const float*)d_in[23];
    const float* gate_w    = (const float*)d_in[24];
    const float* gate_b    = (const float*)d_in[25];
    const float* gl_g      = (const float*)d_in[26];
    const float* gl_b      = (const float*)d_in[27];
    const float* nproj_w   = (const float*)d_in[28];
    const float* nproj_b   = (const float*)d_in[29];

    const int smem_nodeln = (16896 + 2048 + 8192 + 256) * 4;       // 109568
    const int smem_hyper  = (2112*4 + 4224 + 1024 + 33792) * 4;    // 189952
    const int smem_node   = (16896*2 + 2112*5 + 2048*2 + 256*2
                             + 128*4 + 48) * 4;                    // 198080

    cudaFuncSetAttribute(k_node_ln, cudaFuncAttributeMaxDynamicSharedMemorySize, smem_nodeln);
    cudaFuncSetAttribute(k_hyper,   cudaFuncAttributeMaxDynamicSharedMemorySize, smem_hyper);
    cudaFuncSetAttribute(k_node,    cudaFuncAttributeMaxDynamicSharedMemorySize, smem_node);

    k_node_ln<<<576, 512, smem_nodeln>>>(fm, np_g, np_b, sc);
    k_reduce<<<128, 128>>>();
    k_hyper<<<8, 512, smem_hyper>>>(mha_w_in, mha_b_in, mha_w_out, mha_b_out,
                                    ffn_w1, ffn_b1, ffn_w2, ffn_b2,
                                    tnorm_g, tnorm_b, nh_g, nh_b,
                                    hp_w, hp_b, kv_w, kv_b, q_w, q_b,
                                    gate_w, gate_b, nf_g, nf_b);
    k_node<<<576, 512, smem_node>>>(sc, gl_g, gl_b, nproj_w, nproj_b, (float*)d_out);
}

// round 6
// speedup vs baseline: 4.1697x; 1.0561x over previous
#include <cuda_runtime.h>
#include <math.h>

#define BB 8
#define CC 128
#define NN 9216
#define EE 16

// ---------------- scratch ----------------
__device__ float g_node [BB*NN*CC];
__device__ float g_part [BB*72*EE*CC];
__device__ float g_hyper [BB*EE*CC];
__device__ float g_hyperF[BB*EE*CC];
__device__ float g_V [BB*EE*CC];
__device__ float g_Kp[BB*EE*CC];
__device__ float g_kb[BB*EE];
__device__ float g_Hw[BB*EE*CC];
__device__ float g_Vw[BB*EE*CC];
__device__ float g_GH[BB*EE*EE];
__device__ float g_GV[BB*EE*EE];
__device__ float g_hs[BB*EE];
__device__ float g_vs[BB*EE];
__device__ float g_u[CC];
__device__ float g_t[CC];

__device__ __forceinline__ float gelu_exact(float x){
    return 0.5f*x*(1.0f + erff(x*0.70710678118654752f));
}

__device__ __forceinline__ unsigned int f2tf32(float x){
    unsigned int y;
    asm("cvt.rna.tf32.f32 %0, %1;" : "=r"(y) : "f"(x));
    return y;
}

__device__ __forceinline__ void mma_tf32(float* d, const unsigned int* a, const unsigned int* bq){
    asm volatile(
      "mma.sync.aligned.m16n8k8.row.col.f32.tf32.tf32.f32 "
      "{%0,%1,%2,%3}, {%4,%5,%6,%7}, {%8,%9}, {%0,%1,%2,%3};\n"
      : "+f"(d[0]), "+f"(d[1]), "+f"(d[2]), "+f"(d[3])
      : "r"(a[0]), "r"(a[1]), "r"(a[2]), "r"(a[3]), "r"(bq[0]), "r"(bq[1]));
}

// ============ kernel 1: transpose + LayerNorm(node) + agg partials ============
// grid 576 (8*72), block 512, 128 nodes/block
__global__ void __launch_bounds__(512)
k_node_ln(const float* __restrict__ fm,
          const float* __restrict__ gam,
          const float* __restrict__ bet,
          const float* __restrict__ sc)
{
    extern __shared__ float sm[];
    float* tile   = sm;              // 128*132
    float* s_sc   = tile + 16896;    // 2048
    float* s_part = s_sc + 2048;     // 8192
    float* s_mean = s_part + 8192;   // 128
    float* s_rstd = s_mean + 128;    // 128
    int b  = blockIdx.x / 72;
    int n0 = (blockIdx.x % 72) * 128;
    int tid = threadIdx.x;

    for (int i = tid; i < 16384; i += 512){
        int c = i >> 7, n = i & 127;
        tile[n*132 + c] = fm[(size_t)(b*CC + c)*NN + n0 + n];
    }
    for (int i = tid; i < 2048; i += 512)
        s_sc[i] = sc[(size_t)(b*NN + n0)*EE + i];
    __syncthreads();

    int w = tid >> 5, lane = tid & 31;
    for (int n = w*8; n < w*8 + 8; n++){
        float v0 = tile[n*132+lane],    v1 = tile[n*132+lane+32];
        float v2 = tile[n*132+lane+64], v3 = tile[n*132+lane+96];
        float s = v0+v1+v2+v3;
        for (int o=16;o;o>>=1) s += __shfl_xor_sync(0xffffffffu, s, o);
        float m = s * (1.0f/128.0f);
        float d0=v0-m, d1=v1-m, d2=v2-m, d3=v3-m;
        float q = d0*d0+d1*d1+d2*d2+d3*d3;
        for (int o=16;o;o>>=1) q += __shfl_xor_sync(0xffffffffu, q, o);
        if (lane == 0){ s_mean[n]=m; s_rstd[n]=rsqrtf(q*(1.0f/128.0f)+1e-5f); }
    }
    __syncthreads();

    int c = tid & 127, q = tid >> 7;     // q in 0..3, 32 nodes each
    float gg = gam[c], bb = bet[c];
    float acc[16];
    #pragma unroll
    for (int e=0;e<16;e++) acc[e]=0.f;
    for (int n = q*32; n < q*32 + 32; n++){
        float v = (tile[n*132+c]-s_mean[n])*s_rstd[n]*gg + bb;
        g_node[(size_t)(b*NN + n0 + n)*CC + c] = v;
        #pragma unroll
        for (int e=0;e<16;e++) acc[e] += s_sc[n*16+e]*v;
    }
    #pragma unroll
    for (int e=0;e<16;e++) s_part[q*2048 + e*128 + c] = acc[e];
    __syncthreads();

    for (int i = tid; i < 2048; i += 512){
        float s = s_part[i] + s_part[2048+i] + s_part[4096+i] + s_part[6144+i];
        g_part[(size_t)(b*72 + (blockIdx.x%72))*2048 + i] = s;
    }
}

// ============ kernel 2: reduce agg partials ============
__global__ void k_reduce()
{
    int i = blockIdx.x*128 + threadIdx.x;   // 16384 total
    int b = i >> 11, rem = i & 2047;
    float s = 0.f;
    #pragma unroll 4
    for (int j = 0; j < 72; j++) s += g_part[(size_t)(b*72 + j)*2048 + rem];
    g_hyper[b*2048 + rem] = s;
}

// ============ kernel 3: hyperedge transformer + per-batch precomputes ============
template<int CIN, int COUT, int ACT>
__device__ __forceinline__ void gemmF(const float* __restrict__ W,
                                      const float* __restrict__ bias,
                                      const float* in, int inPitch,
                                      float* out, int outPitch, float* sw)
{
    const int pitch = CIN + 4;
    const int cin4  = CIN >> 2;
    const float4* W4 = (const float4*)W;
    for (int i = threadIdx.x; i < (COUT*CIN)>>2; i += 512){
        int r = i / cin4, c4 = i - r*cin4;
        ((float4*)(sw + r*pitch))[c4] = W4[i];
    }
    __syncthreads();
    const int logC  = (COUT == 256) ? 8 : 7;
    const int estep = 512 >> logC;
    const int nE    = 16 / estep;
    int j  = threadIdx.x & (COUT-1);
    int e0 = threadIdx.x >> logC;
    const float4* wr = (const float4*)(sw + j*pitch);
    float acc[nE];
    const float4* ar[nE];
    #pragma unroll
    for (int r=0;r<nE;r++){ acc[r]=0.f; ar[r]=(const float4*)(in + (e0 + r*estep)*inPitch); }
    for (int kk = 0; kk < cin4; kk++){
        float4 wv = wr[kk];
        #pragma unroll
        for (int r=0;r<nE;r++){
            float4 av = ar[r][kk];
            acc[r] += av.x*wv.x + av.y*wv.y + av.z*wv.z + av.w*wv.w;
        }
    }
    float bj = bias[j];
    #pragma unroll
    for (int r=0;r<nE;r++){
        float v = acc[r] + bj;
        if (ACT) v = gelu_exact(v);
        out[(e0 + r*estep)*outPitch + j] = v;
    }
    __syncthreads();
}

__device__ __forceinline__ void ln16_128(const float* a, const float* r, int pitch,
                                         const float* __restrict__ g,
                                         const float* __restrict__ b,
                                         float* out, int outPitch)
{
    int w = threadIdx.x >> 5, lane = threadIdx.x & 31;
    if (w < 16){
        float v[4]; float s = 0.f;
        #pragma unroll
        for (int i=0;i<4;i++){
            float x = a[w*pitch + lane + 32*i];
            if (r) x += r[w*pitch + lane + 32*i];
            v[i] = x; s += x;
        }
        for (int o=16;o;o>>=1) s += __shfl_xor_sync(0xffffffffu, s, o);
        float m = s*(1.f/128.f), q = 0.f;
        #pragma unroll
        for (int i=0;i<4;i++){ float d=v[i]-m; q += d*d; }
        for (int o=16;o;o>>=1) q += __shfl_xor_sync(0xffffffffu, q, o);
        float rs = rsqrtf(q*(1.f/128.f)+1e-5f);
        #pragma unroll
        for (int i=0;i<4;i++)
            out[w*outPitch + lane + 32*i] = (v[i]-m)*rs*g[lane+32*i] + b[lane+32*i];
    }
    __syncthreads();
}

__global__ void __launch_bounds__(512)
k_hyper(const float* __restrict__ mha_w_in, const float* __restrict__ mha_b_in,
        const float* __restrict__ mha_w_out, const float* __restrict__ mha_b_out,
        const float* __restrict__ ffn_w1, const float* __restrict__ ffn_b1,
        const float* __restrict__ ffn_w2, const float* __restrict__ ffn_b2,
        const float* __restrict__ tnorm_g, const float* __restrict__ tnorm_b,
        const float* __restrict__ nh_g, const float* __restrict__ nh_b,
        const float* __restrict__ hp_w, const float* __restrict__ hp_b,
        const float* __restrict__ kv_w, const float* __restrict__ kv_b,
        const float* __restrict__ q_w, const float* __restrict__ q_b,
        const float* __restrict__ gate_w, const float* __restrict__ gate_b,
        const float* __restrict__ nf_g, const float* __restrict__ nf_b)
{
    extern __shared__ float sm[];
    float* s0   = sm;            // 16*132
    float* s1   = s0 + 2112;
    float* s2   = s1 + 2112;
    float* s3   = s2 + 2112;
    float* sh   = s3 + 2112;     // 16*264
    float* satt = sh + 4224;     // 1024
    float* sw   = satt + 1024;   // 33792 floats
    int b = blockIdx.x, tid = threadIdx.x;

    for (int i = tid; i < 2048; i += 512)
        s0[(i>>7)*132 + (i&127)] = g_hyper[b*2048 + i];
    __syncthreads();

    gemmF<128,128,0>(mha_w_in,           mha_b_in,     s0,132, s1,132, sw);
    gemmF<128,128,0>(mha_w_in + 128*128, mha_b_in+128, s0,132, s2,132, sw);
    gemmF<128,128,0>(mha_w_in + 256*128, mha_b_in+256, s0,132, s3,132, sw);

    for (int p = tid; p < 1024; p += 512){
        int h = p>>8, e1 = (p>>4)&15, e2 = p&15;
        const float* qr = s1 + e1*132 + h*32;
        const float* kr = s2 + e2*132 + h*32;
        float acc = 0.f;
        #pragma unroll
        for (int d=0; d<32; d++) acc += qr[d]*kr[d];
        satt[p] = acc * 0.17677669529663687f;
    }
    __syncthreads();
    if (tid < 64){
        float* row = satt + tid*16;
        float mx = row[0];
        #pragma unroll
        for (int e=1;e<16;e++) mx = fmaxf(mx, row[e]);
        float s = 0.f;
        #pragma unroll
        for (int e=0;e<16;e++){ float v = expf(row[e]-mx); row[e]=v; s+=v; }
        float inv = 1.f/s;
        #pragma unroll
        for (int e=0;e<16;e++) row[e] *= inv;
    }
    __syncthreads();
    for (int p = tid; p < 2048; p += 512){
        int e = p>>7, c = p&127, h = c>>5;
        float acc = 0.f;
        #pragma unroll
        for (int e2=0;e2<16;e2++) acc += satt[(h*16+e)*16 + e2] * s3[e2*132 + c];
        s1[e*132 + c] = acc;
    }
    __syncthreads();
    gemmF<128,128,0>(mha_w_out, mha_b_out, s1,132, s2,132, sw);
    ln16_128(s0, s2, 132, tnorm_g, tnorm_b, s3, 132);
    gemmF<128,256,1>(ffn_w1, ffn_b1, s3,132, sh,264, sw);
    gemmF<256,128,0>(ffn_w2, ffn_b2, sh,264, s1,132, sw);
    ln16_128(s3, s1, 132, tnorm_g, tnorm_b, s2, 132);
    ln16_128(s2, (const float*)0, 132, nh_g, nh_b, s3, 132);
    gemmF<128,128,1>(hp_w, hp_b, s3,132, s0,132, sw);               // H -> s0
    gemmF<128,128,0>(kv_w,           kv_b,     s0,132, s1,132, sw); // K -> s1
    gemmF<128,128,0>(kv_w + 128*128, kv_b+128, s0,132, s2,132, sw); // V -> s2

    // Kp[e,c] (pre-scaled) and kb[e]
    {
        const float4* W4 = (const float4*)q_w;
        for (int i = tid; i < 4096; i += 512){
            int r = i >> 5, c4 = i & 31;
            ((float4*)(sw + r*132))[c4] = W4[i];
        }
        __syncthreads();
        const float scl = 0.08838834764831845f;
        for (int o = tid; o < 2048; o += 512){
            int e = o>>7, k = o&127;
            float acc = 0.f;
            for (int c = 0; c < 128; c++) acc += s1[e*132+c]*sw[c*132+k];
            g_Kp[b*2048 + o] = acc * scl;
        }
        if (tid < 16){
            float acc = 0.f;
            for (int c = 0; c < 128; c++) acc += q_b[c]*s1[tid*132+c];
            g_kb[b*16 + tid] = acc * scl;
        }
    }
    __syncthreads();

    // gate decomposition precomputes
    {
        const float4* GW4 = (const float4*)gate_w;
        for (int i = tid; i < 8192; i += 512){
            int r = i >> 6, c4 = i & 63;
            ((float4*)(sw + r*264))[c4] = GW4[i];
        }
        __syncthreads();
        if (tid < 128){
            float t = gate_b[tid];
            for (int c = 0; c < 256; c++) t += nf_b[c]*sw[tid*264+c];
            g_t[tid] = t;
        }
        __syncthreads();
        for (int i = tid; i < 32768; i += 512){
            int r = i >> 8, c = i & 255;
            sw[r*264+c] *= nf_g[c];
        }
        __syncthreads();
        if (tid < 128){
            float u = 0.f;
            for (int c = 0; c < 256; c++) u += sw[tid*264+c];
            g_u[tid] = u;
        }
        for (int p = tid; p < 2048; p += 512){
            int j = p & 127, e = p >> 7;
            const float4* hr = (const float4*)(s0 + e*132);
            const float4* vr = (const float4*)(s2 + e*132);
            const float4* w1 = (const float4*)(sw + j*264);
            const float4* w2 = (const float4*)(sw + j*264 + 128);
            float a1 = 0.f, a2 = 0.f;
            #pragma unroll 8
            for (int kk = 0; kk < 32; kk++){
                float4 h = hr[kk], w = w1[kk];
                a1 += h.x*w.x + h.y*w.y + h.z*w.z + h.w*w.w;
                float4 v = vr[kk], x = w2[kk];
                a2 += v.x*x.x + v.y*x.y + v.z*x.z + v.w*x.w;
            }
            g_Hw[b*2048+p] = a1; g_Vw[b*2048+p] = a2;
        }
        if (tid < 512){
            int q = tid;
            const float* A = (q < 256) ? s0 : s2;
            int qq = q & 255;
            int e = qq >> 4, f = qq & 15;
            const float4* r1 = (const float4*)(A + e*132);
            const float4* r2 = (const float4*)(A + f*132);
            float acc = 0.f;
            #pragma unroll 8
            for (int kk = 0; kk < 32; kk++){
                float4 a = r1[kk], c = r2[kk];
                acc += a.x*c.x + a.y*c.y + a.z*c.z + a.w*c.w;
            }
            if (q < 256) g_GH[b*256+qq] = acc; else g_GV[b*256+qq] = acc;
        }
        if (tid < 32){
            int e = tid & 15;
            const float* A = (tid < 16) ? s0 : s2;
            float s = 0.f;
            for (int c = 0; c < 128; c++) s += A[e*132+c];
            if (tid < 16) g_hs[b*16+e] = s; else g_vs[b*16+e] = s;
        }
    }

    for (int i = tid; i < 2048; i += 512){
        int e = i>>7, c = i&127, o = b*2048 + i;
        g_hyperF[o] = s0[e*132+c];
        g_V[o]      = s2[e*132+c];
    }
}

// ============ kernel 4: FUSED per-node pipeline (nproj on tensor cores) ============
// grid 576 (8*72), block 512, 128 nodes/block
__global__ void __launch_bounds__(512)
k_node(const float* __restrict__ sc,
       const float* __restrict__ gl_g, const float* __restrict__ gl_b,
       const float* __restrict__ nproj_w, const float* __restrict__ nproj_b,
       float* __restrict__ out)
{
    extern __shared__ float sm[];
    float* s_node = sm;              // 16896 (128*132)
    float* s_ov   = s_node + 16896;  // 16896 overlay: gate, then nproj weights
    float* s_Kp   = s_ov   + 16896;  // 2112
    float* s_H    = s_Kp   + 2112;
    float* s_V    = s_H    + 2112;
    float* s_Hw   = s_V    + 2112;
    float* s_Vw   = s_Hw   + 2112;
    float* s_att  = s_Vw   + 2112;   // 2048 (128*16)
    float* s_sc   = s_att  + 2048;   // 2048
    float* s_GH   = s_sc   + 2048;   // 256
    float* s_GV   = s_GH   + 256;
    float* s_u    = s_GV   + 256;    // 128
    float* s_t    = s_u    + 128;
    float* s_m    = s_t    + 128;    // 128
    float* s_rs   = s_m    + 128;
    float* s_hs   = s_rs   + 128;    // 16
    float* s_vs   = s_hs   + 16;
    float* s_kb   = s_vs   + 16;

    int b  = blockIdx.x / 72;
    int n0 = (blockIdx.x % 72) * 128;
    int tid = threadIdx.x;

    // ---- stage (not s_ov) ----
    for (int i4 = tid; i4 < 4096; i4 += 512){
        int n = i4 >> 5, c4 = i4 & 31;
        ((float4*)(s_node + n*132))[c4] =
            ((const float4*)(g_node + (size_t)(b*NN + n0 + n)*CC))[c4];
    }
    {
        int i4 = tid;
        if (i4 < 512){
            int e = i4 >> 5, c4 = i4 & 31;
            ((float4*)(s_Kp + e*132))[c4] = ((const float4*)(g_Kp    + b*2048))[i4];
            ((float4*)(s_H  + e*132))[c4] = ((const float4*)(g_hyperF+ b*2048))[i4];
            ((float4*)(s_V  + e*132))[c4] = ((const float4*)(g_V     + b*2048))[i4];
            ((float4*)(s_Hw + e*132))[c4] = ((const float4*)(g_Hw    + b*2048))[i4];
            ((float4*)(s_Vw + e*132))[c4] = ((const float4*)(g_Vw    + b*2048))[i4];
        }
        if (i4 < 512) ((float4*)s_sc)[i4] = ((const float4*)(sc + (size_t)(b*NN + n0)*16))[i4];
        if (i4 < 64){
            ((float4*)s_GH)[i4] = ((const float4*)(g_GH + b*256))[i4];
            ((float4*)s_GV)[i4] = ((const float4*)(g_GV + b*256))[i4];
        }
        if (i4 < 32){
            ((float4*)s_u)[i4] = ((const float4*)g_u)[i4];
            ((float4*)s_t)[i4] = ((const float4*)g_t)[i4];
        }
        if (i4 < 16){ s_hs[i4]=g_hs[b*16+i4]; s_vs[i4]=g_vs[b*16+i4]; s_kb[i4]=g_kb[b*16+i4]; }
    }
    __syncthreads();

    // ---- logits: att_pre[n,e] = node[n].Kp[e] + kb[e] ----
    {
        int n = tid >> 2, q = tid & 3;
        const float4* nr = (const float4*)(s_node + n*132);
        float acc[4] = {0.f,0.f,0.f,0.f};
        const float4* kp0 = (const float4*)(s_Kp + (q*4+0)*132);
        const float4* kp1 = (const float4*)(s_Kp + (q*4+1)*132);
        const float4* kp2 = (const float4*)(s_Kp + (q*4+2)*132);
        const float4* kp3 = (const float4*)(s_Kp + (q*4+3)*132);
        #pragma unroll 8
        for (int kk = 0; kk < 32; kk++){
            float4 a = nr[kk];
            float4 k0 = kp0[kk], k1 = kp1[kk], k2 = kp2[kk], k3 = kp3[kk];
            acc[0] += a.x*k0.x + a.y*k0.y + a.z*k0.z + a.w*k0.w;
            acc[1] += a.x*k1.x + a.y*k1.y + a.z*k1.z + a.w*k1.w;
            acc[2] += a.x*k2.x + a.y*k2.y + a.z*k2.z + a.w*k2.w;
            acc[3] += a.x*k3.x + a.y*k3.y + a.z*k3.z + a.w*k3.w;
        }
        #pragma unroll
        for (int i=0;i<4;i++) s_att[n*16 + q*4 + i] = acc[i] + s_kb[q*4+i];
    }
    __syncthreads();

    // ---- softmax + LN256 stats via Gram matrices ----
    if (tid < 128){
        int n = tid;
        float scv[16], atv[16];
        float* row = s_att + n*16;
        float mx = row[0];
        #pragma unroll
        for (int e=1;e<16;e++) mx = fmaxf(mx, row[e]);
        float s = 0.f;
        #pragma unroll
        for (int e=0;e<16;e++){ float v = expf(row[e]-mx); atv[e]=v; s+=v; }
        float inv = 1.f/s;
        #pragma unroll
        for (int e=0;e<16;e++){ atv[e] *= inv; row[e] = atv[e]; scv[e] = s_sc[n*16+e]; }
        float mean = 0.f;
        #pragma unroll
        for (int e=0;e<16;e++) mean += scv[e]*s_hs[e] + atv[e]*s_vs[e];
        mean *= (1.f/256.f);
        float ssq = 0.f;
        #pragma unroll
        for (int e=0;e<16;e++){
            float t1 = 0.f, t2 = 0.f;
            #pragma unroll
            for (int f=0;f<16;f++){
                t1 += scv[f]*s_GH[e*16+f];
                t2 += atv[f]*s_GV[e*16+f];
            }
            ssq += scv[e]*t1 + atv[e]*t2;
        }
        float var = ssq*(1.f/256.f) - mean*mean;
        s_m[n] = mean;
        s_rs[n] = rsqrtf(var + 1e-5f);
    }
    __syncthreads();

    // ---- gate linear via rank-16 into overlay ----
    {
        float* s_gate = s_ov;
        int j = tid & 127, g = tid >> 7;
        float uj = s_u[j], tj = s_t[j];
        for (int blk = 0; blk < 4; blk++){
            int nb = g*32 + blk*8;
            float acc[8] = {0,0,0,0,0,0,0,0};
            #pragma unroll
            for (int kk = 0; kk < 4; kk++){
                float b0 = s_Hw[(kk*4+0)*132 + j];
                float b1 = s_Hw[(kk*4+1)*132 + j];
                float b2 = s_Hw[(kk*4+2)*132 + j];
                float b3 = s_Hw[(kk*4+3)*132 + j];
                #pragma unroll
                for (int i=0;i<8;i++){
                    float4 a = ((const float4*)(s_sc + (nb+i)*16))[kk];
                    acc[i] += a.x*b0 + a.y*b1 + a.z*b2 + a.w*b3;
                }
            }
            #pragma unroll
            for (int kk = 0; kk < 4; kk++){
                float b0 = s_Vw[(kk*4+0)*132 + j];
                float b1 = s_Vw[(kk*4+1)*132 + j];
                float b2 = s_Vw[(kk*4+2)*132 + j];
                float b3 = s_Vw[(kk*4+3)*132 + j];
                #pragma unroll
                for (int i=0;i<8;i++){
                    float4 a = ((const float4*)(s_att + (nb+i)*16))[kk];
                    acc[i] += a.x*b0 + a.y*b1 + a.z*b2 + a.w*b3;
                }
            }
            #pragma unroll
            for (int i=0;i<8;i++){
                int n = nb + i;
                s_gate[n*132 + j] = s_rs[n]*(acc[i] - s_m[n]*uj) + tj;
            }
        }
    }
    __syncthreads();

    // ---- LN128 + sigmoid on gate rows ----
    {
        float* s_gate = s_ov;
        int w = tid >> 5, lane = tid & 31;
        float g0 = gl_g[lane], g1 = gl_g[lane+32], g2 = gl_g[lane+64], g3 = gl_g[lane+96];
        float b0 = gl_b[lane], b1 = gl_b[lane+32], b2 = gl_b[lane+64], b3 = gl_b[lane+96];
        for (int r = w*8; r < w*8 + 8; r++){
            float v0 = s_gate[r*132+lane],    v1 = s_gate[r*132+lane+32];
            float v2 = s_gate[r*132+lane+64], v3 = s_gate[r*132+lane+96];
            float s = v0+v1+v2+v3;
            for (int o=16;o;o>>=1) s += __shfl_xor_sync(0xffffffffu, s, o);
            float m = s*(1.f/128.f);
            float d0=v0-m, d1=v1-m, d2=v2-m, d3=v3-m;
            float q = d0*d0+d1*d1+d2*d2+d3*d3;
            for (int o=16;o;o>>=1) q += __shfl_xor_sync(0xffffffffu, q, o);
            float rs = rsqrtf(q*(1.f/128.f)+1e-5f);
            s_gate[r*132+lane]    = 1.f/(1.f+expf(-(d0*rs*g0+b0)));
            s_gate[r*132+lane+32] = 1.f/(1.f+expf(-(d1*rs*g1+b1)));
            s_gate[r*132+lane+64] = 1.f/(1.f+expf(-(d2*rs*g2+b2)));
            s_gate[r*132+lane+96] = 1.f/(1.f+expf(-(d3*rs*g3+b3)));
        }
    }
    __syncthreads();

    // ---- upd = node + g*intra + (1-g)*cross (in place into s_node) ----
    {
        float* s_gate = s_ov;
        int c = tid & 127, g = tid >> 7;
        float hcol[16], vcol[16];
        #pragma unroll
        for (int e=0;e<16;e++){ hcol[e] = s_H[e*132+c]; vcol[e] = s_V[e*132+c]; }
        for (int n = g*32; n < g*32 + 32; n++){
            float intra = 0.f, cross = 0.f;
            #pragma unroll
            for (int kk=0; kk<4; kk++){
                float4 a = ((const float4*)(s_sc  + n*16))[kk];
                float4 t = ((const float4*)(s_att + n*16))[kk];
                intra += a.x*hcol[kk*4] + a.y*hcol[kk*4+1] + a.z*hcol[kk*4+2] + a.w*hcol[kk*4+3];
                cross += t.x*vcol[kk*4] + t.y*vcol[kk*4+1] + t.z*vcol[kk*4+2] + t.w*vcol[kk*4+3];
            }
            float gt = s_gate[n*132+c];
            s_node[n*132+c] = s_node[n*132+c] + gt*intra + (1.f-gt)*cross;
        }
    }
    __syncthreads();

    // ---- stage nproj weights into overlay (gate dead now) ----
    for (int i4 = tid; i4 < 4096; i4 += 512){
        int r = i4 >> 5, k4 = i4 & 31;
        ((float4*)(s_ov + r*132))[k4] = ((const float4*)nproj_w)[i4];
    }
    __syncthreads();

    // ---- nproj via tensor cores: mma.m16n8k8 tf32, 3xTF32 accuracy ----
    // warp w: node tile (w&7)*16, j half (w>>3)*64. Each warp: 16 nodes x 64 channels.
    {
        float* s_w = s_ov;
        int lane = tid & 31, w = tid >> 5;
        int nb  = (w & 7) * 16;
        int jb0 = (w >> 3) * 64;
        int g = lane >> 2, t = lane & 3;
        const float* An0 = s_node + (nb + g)*132;
        const float* An1 = s_node + (nb + g + 8)*132;

        float acc[8][4];
        #pragma unroll
        for (int jt=0;jt<8;jt++){
            acc[jt][0]=0.f; acc[jt][1]=0.f; acc[jt][2]=0.f; acc[jt][3]=0.f;
        }

        #pragma unroll 2
        for (int kc = 0; kc < 16; kc++){
            int kb = kc*8;
            float a0 = An0[kb + t];
            float a1 = An1[kb + t];
            float a2 = An0[kb + t + 4];
            float a3 = An1[kb + t + 4];
            unsigned int ah[4] = { f2tf32(a0), f2tf32(a1), f2tf32(a2), f2tf32(a3) };
            unsigned int al[4] = {
                f2tf32(a0 - __uint_as_float(ah[0])),
                f2tf32(a1 - __uint_as_float(ah[1])),
                f2tf32(a2 - __uint_as_float(ah[2])),
                f2tf32(a3 - __uint_as_float(ah[3])) };
            #pragma unroll
            for (int jt = 0; jt < 8; jt++){
                const float* Bp = s_w + (jb0 + jt*8 + g)*132 + kb;
                float w0 = Bp[t];
                float w1 = Bp[t + 4];
                unsigned int bh[2] = { f2tf32(w0), f2tf32(w1) };
                unsigned int bl[2] = {
                    f2tf32(w0 - __uint_as_float(bh[0])),
                    f2tf32(w1 - __uint_as_float(bh[1])) };
                mma_tf32(acc[jt], ah, bh);
                mma_tf32(acc[jt], ah, bl);
                mma_tf32(acc[jt], al, bh);
            }
        }

        // bias + gelu + transposed store: D(node, j) -> out[(b*CC+j)*NN + node]
        int nlo = n0 + nb + g;
        int nhi = nlo + 8;
        #pragma unroll
        for (int jt = 0; jt < 8; jt++){
            int j0 = jb0 + jt*8 + 2*t;
            float bias0 = nproj_b[j0], bias1 = nproj_b[j0+1];
            out[(size_t)(b*CC + j0    )*NN + nlo] = gelu_exact(acc[jt][0] + bias0);
            out[(size_t)(b*CC + j0 + 1)*NN + nlo] = gelu_exact(acc[jt][1] + bias1);
            out[(size_t)(b*CC + j0    )*NN + nhi] = gelu_exact(acc[jt][2] + bias0);
            out[(size_t)(b*CC + j0 + 1)*NN + nhi] = gelu_exact(acc[jt][3] + bias1);
        }
    }
}

// ---------------- launch ----------------
extern "C" void kernel_launch(void* const* d_in, const int* in_sizes, int n_in,
                              void* d_out, int out_size)
{
    const float* fm        = (const float*)d_in[0];
    const float* sc        = (const float*)d_in[1];
    const float* np_g      = (const float*)d_in[2];
    const float* np_b      = (const float*)d_in[3];
    const float* mha_w_in  = (const float*)d_in[4];
    const float* mha_b_in  = (const float*)d_in[5];
    const float* mha_w_out = (const float*)d_in[6];
    const float* mha_b_out = (const float*)d_in[7];
    const float* ffn_w1    = (const float*)d_in[8];
    const float* ffn_b1    = (const float*)d_in[9];
    const float* ffn_w2    = (const float*)d_in[10];
    const float* ffn_b2    = (const float*)d_in[11];
    const float* tnorm_g   = (const float*)d_in[12];
    const float* tnorm_b   = (const float*)d_in[13];
    const float* nh_g      = (const float*)d_in[14];
    const float* nh_b      = (const float*)d_in[15];
    const float* hp_w      = (const float*)d_in[16];
    const float* hp_b      = (const float*)d_in[17];
    const float* q_w       = (const float*)d_in[18];
    const float* q_b       = (const float*)d_in[19];
    const float* kv_w      = (const float*)d_in[20];
    const float* kv_b      = (const float*)d_in[21];
    const float* nf_g      = (const float*)d_in[22];
    const float* nf_b      = (const float*)d_in[23];
    const float* gate_w    = (const float*)d_in[24];
    const float* gate_b    = (const float*)d_in[25];
    const float* gl_g      = (const float*)d_in[26];
    const float* gl_b      = (const float*)d_in[27];
    const float* nproj_w   = (const float*)d_in[28];
    const float* nproj_b   = (const float*)d_in[29];

    const int smem_nodeln = (16896 + 2048 + 8192 + 256) * 4;       // 109568
    const int smem_hyper  = (2112*4 + 4224 + 1024 + 33792) * 4;    // 189952
    const int smem_node   = (16896*2 + 2112*5 + 2048*2 + 256*2
                             + 128*4 + 48) * 4;                    // 198080

    cudaFuncSetAttribute(k_node_ln, cudaFuncAttributeMaxDynamicSharedMemorySize, smem_nodeln);
    cudaFuncSetAttribute(k_hyper,   cudaFuncAttributeMaxDynamicSharedMemorySize, smem_hyper);
    cudaFuncSetAttribute(k_node,    cudaFuncAttributeMaxDynamicSharedMemorySize, smem_node);

    k_node_ln<<<576, 512, smem_nodeln>>>(fm, np_g, np_b, sc);
    k_reduce<<<128, 128>>>();
    k_hyper<<<8, 512, smem_hyper>>>(mha_w_in, mha_b_in, mha_w_out, mha_b_out,
                                    ffn_w1, ffn_b1, ffn_w2, ffn_b2,
                                    tnorm_g, tnorm_b, nh_g, nh_b,
                                    hp_w, hp_b, kv_w, kv_b, q_w, q_b,
                                    gate_w, gate_b, nf_g, nf_b);
    k_node<<<576, 512, smem_node>>>(sc, gl_g, gl_b, nproj_w, nproj_b, (float*)d_out);
}

// round 7
// speedup vs baseline: 4.4084x; 1.0572x over previous
#include <cuda_runtime.h>
#include <cuda_bf16.h>
#include <math.h>

#define BB 8
#define CC 128
#define NN 9216
#define EE 16

// ---------------- scratch ----------------
__device__ float g_node [BB*NN*CC];
__device__ float g_part [BB*72*EE*CC];
__device__ float g_hyper [BB*EE*CC];
__device__ float g_hyperF[BB*EE*CC];
__device__ float g_K [BB*EE*CC];
__device__ float g_V [BB*EE*CC];
__device__ float g_Kp[BB*EE*CC];
__device__ float g_kb[BB*EE];
__device__ float g_Hw[BB*EE*CC];
__device__ float g_Vw[BB*EE*CC];
__device__ float g_GH[BB*EE*EE];
__device__ float g_GV[BB*EE*EE];
__device__ float g_hs[BB*EE];
__device__ float g_vs[BB*EE];
__device__ float g_u[CC];
__device__ float g_t[CC];
__device__ unsigned int g_whp[CC*64];   // nproj_w bf16 hi, pairs along k
__device__ unsigned int g_wlp[CC*64];   // nproj_w bf16 lo

__device__ __forceinline__ float gelu_exact(float x){
    return 0.5f*x*(1.0f + erff(x*0.70710678118654752f));
}

__device__ __forceinline__ void mma_bf16(float* d, const unsigned int* a,
                                         unsigned int b0, unsigned int b1){
    asm volatile(
      "mma.sync.aligned.m16n8k16.row.col.f32.bf16.bf16.f32 "
      "{%0,%1,%2,%3}, {%4,%5,%6,%7}, {%8,%9}, {%0,%1,%2,%3};\n"
      : "+f"(d[0]), "+f"(d[1]), "+f"(d[2]), "+f"(d[3])
      : "r"(a[0]), "r"(a[1]), "r"(a[2]), "r"(a[3]), "r"(b0), "r"(b1));
}

// split float2 -> bf16x2 hi + bf16x2 lo
__device__ __forceinline__ void bf16_split2(float2 v, unsigned int& hi, unsigned int& lo){
    __nv_bfloat162 h = __float22bfloat162_rn(v);
    float2 back = __bfloat1622float2(h);
    __nv_bfloat162 l = __float22bfloat162_rn(make_float2(v.x - back.x, v.y - back.y));
    hi = *(unsigned int*)&h;
    lo = *(unsigned int*)&l;
}

// ============ kernel 1: transpose + LayerNorm(node) + agg partials ============
__global__ void __launch_bounds__(512)
k_node_ln(const float* __restrict__ fm,
          const float* __restrict__ gam,
          const float* __restrict__ bet,
          const float* __restrict__ sc)
{
    extern __shared__ float sm[];
    float* tile   = sm;              // 128*132
    float* s_sc   = tile + 16896;    // 2048
    float* s_part = s_sc + 2048;     // 8192
    float* s_mean = s_part + 8192;   // 128
    float* s_rstd = s_mean + 128;    // 128
    int b  = blockIdx.x / 72;
    int n0 = (blockIdx.x % 72) * 128;
    int tid = threadIdx.x;

    for (int i = tid; i < 16384; i += 512){
        int c = i >> 7, n = i & 127;
        tile[n*132 + c] = fm[(size_t)(b*CC + c)*NN + n0 + n];
    }
    for (int i = tid; i < 2048; i += 512)
        s_sc[i] = sc[(size_t)(b*NN + n0)*EE + i];
    __syncthreads();

    int w = tid >> 5, lane = tid & 31;
    for (int n = w*8; n < w*8 + 8; n++){
        float v0 = tile[n*132+lane],    v1 = tile[n*132+lane+32];
        float v2 = tile[n*132+lane+64], v3 = tile[n*132+lane+96];
        float s = v0+v1+v2+v3;
        for (int o=16;o;o>>=1) s += __shfl_xor_sync(0xffffffffu, s, o);
        float m = s * (1.0f/128.0f);
        float d0=v0-m, d1=v1-m, d2=v2-m, d3=v3-m;
        float q = d0*d0+d1*d1+d2*d2+d3*d3;
        for (int o=16;o;o>>=1) q += __shfl_xor_sync(0xffffffffu, q, o);
        if (lane == 0){ s_mean[n]=m; s_rstd[n]=rsqrtf(q*(1.0f/128.0f)+1e-5f); }
    }
    __syncthreads();

    int c = tid & 127, q = tid >> 7;
    float gg = gam[c], bb = bet[c];
    float acc[16];
    #pragma unroll
    for (int e=0;e<16;e++) acc[e]=0.f;
    for (int n = q*32; n < q*32 + 32; n++){
        float v = (tile[n*132+c]-s_mean[n])*s_rstd[n]*gg + bb;
        g_node[(size_t)(b*NN + n0 + n)*CC + c] = v;
        #pragma unroll
        for (int e=0;e<16;e++) acc[e] += s_sc[n*16+e]*v;
    }
    #pragma unroll
    for (int e=0;e<16;e++) s_part[q*2048 + e*128 + c] = acc[e];
    __syncthreads();

    for (int i = tid; i < 2048; i += 512){
        float s = s_part[i] + s_part[2048+i] + s_part[4096+i] + s_part[6144+i];
        g_part[(size_t)(b*72 + (blockIdx.x%72))*2048 + i] = s;
    }
}

// ============ kernel 2: reduce agg partials ============
__global__ void k_reduce()
{
    int i = blockIdx.x*128 + threadIdx.x;
    int b = i >> 11, rem = i & 2047;
    float s = 0.f;
    #pragma unroll 4
    for (int j = 0; j < 72; j++) s += g_part[(size_t)(b*72 + j)*2048 + rem];
    g_hyper[b*2048 + rem] = s;
}

// ============ kernel 3: hyperedge transformer (ends at H,K,V) ============
template<int CIN, int COUT, int ACT>
__device__ __forceinline__ void gemmF(const float* __restrict__ W,
                                      const float* __restrict__ bias,
                                      const float* in, int inPitch,
                                      float* out, int outPitch, float* sw)
{
    const int pitch = CIN + 4;
    const int cin4  = CIN >> 2;
    const float4* W4 = (const float4*)W;
    for (int i = threadIdx.x; i < (COUT*CIN)>>2; i += 512){
        int r = i / cin4, c4 = i - r*cin4;
        ((float4*)(sw + r*pitch))[c4] = W4[i];
    }
    __syncthreads();
    const int logC  = (COUT == 256) ? 8 : 7;
    const int estep = 512 >> logC;
    const int nE    = 16 / estep;
    int j  = threadIdx.x & (COUT-1);
    int e0 = threadIdx.x >> logC;
    const float4* wr = (const float4*)(sw + j*pitch);
    float acc[nE];
    const float4* ar[nE];
    #pragma unroll
    for (int r=0;r<nE;r++){ acc[r]=0.f; ar[r]=(const float4*)(in + (e0 + r*estep)*inPitch); }
    for (int kk = 0; kk < cin4; kk++){
        float4 wv = wr[kk];
        #pragma unroll
        for (int r=0;r<nE;r++){
            float4 av = ar[r][kk];
            acc[r] += av.x*wv.x + av.y*wv.y + av.z*wv.z + av.w*wv.w;
        }
    }
    float bj = bias[j];
    #pragma unroll
    for (int r=0;r<nE;r++){
        float v = acc[r] + bj;
        if (ACT) v = gelu_exact(v);
        out[(e0 + r*estep)*outPitch + j] = v;
    }
    __syncthreads();
}

__device__ __forceinline__ void ln16_128(const float* a, const float* r, int pitch,
                                         const float* __restrict__ g,
                                         const float* __restrict__ b,
                                         float* out, int outPitch)
{
    int w = threadIdx.x >> 5, lane = threadIdx.x & 31;
    if (w < 16){
        float v[4]; float s = 0.f;
        #pragma unroll
        for (int i=0;i<4;i++){
            float x = a[w*pitch + lane + 32*i];
            if (r) x += r[w*pitch + lane + 32*i];
            v[i] = x; s += x;
        }
        for (int o=16;o;o>>=1) s += __shfl_xor_sync(0xffffffffu, s, o);
        float m = s*(1.f/128.f), q = 0.f;
        #pragma unroll
        for (int i=0;i<4;i++){ float d=v[i]-m; q += d*d; }
        for (int o=16;o;o>>=1) q += __shfl_xor_sync(0xffffffffu, q, o);
        float rs = rsqrtf(q*(1.f/128.f)+1e-5f);
        #pragma unroll
        for (int i=0;i<4;i++)
            out[w*outPitch + lane + 32*i] = (v[i]-m)*rs*g[lane+32*i] + b[lane+32*i];
    }
    __syncthreads();
}

__global__ void __launch_bounds__(512)
k_hyper(const float* __restrict__ mha_w_in, const float* __restrict__ mha_b_in,
        const float* __restrict__ mha_w_out, const float* __restrict__ mha_b_out,
        const float* __restrict__ ffn_w1, const float* __restrict__ ffn_b1,
        const float* __restrict__ ffn_w2, const float* __restrict__ ffn_b2,
        const float* __restrict__ tnorm_g, const float* __restrict__ tnorm_b,
        const float* __restrict__ nh_g, const float* __restrict__ nh_b,
        const float* __restrict__ hp_w, const float* __restrict__ hp_b,
        const float* __restrict__ kv_w, const float* __restrict__ kv_b)
{
    extern __shared__ float sm[];
    float* s0   = sm;            // 16*132
    float* s1   = s0 + 2112;
    float* s2   = s1 + 2112;
    float* s3   = s2 + 2112;
    float* sh   = s3 + 2112;     // 16*264
    float* satt = sh + 4224;     // 1024
    float* sw   = satt + 1024;   // 33792
    int b = blockIdx.x, tid = threadIdx.x;

    for (int i = tid; i < 2048; i += 512)
        s0[(i>>7)*132 + (i&127)] = g_hyper[b*2048 + i];
    __syncthreads();

    gemmF<128,128,0>(mha_w_in,           mha_b_in,     s0,132, s1,132, sw);
    gemmF<128,128,0>(mha_w_in + 128*128, mha_b_in+128, s0,132, s2,132, sw);
    gemmF<128,128,0>(mha_w_in + 256*128, mha_b_in+256, s0,132, s3,132, sw);

    for (int p = tid; p < 1024; p += 512){
        int h = p>>8, e1 = (p>>4)&15, e2 = p&15;
        const float* qr = s1 + e1*132 + h*32;
        const float* kr = s2 + e2*132 + h*32;
        float acc = 0.f;
        #pragma unroll
        for (int d=0; d<32; d++) acc += qr[d]*kr[d];
        satt[p] = acc * 0.17677669529663687f;
    }
    __syncthreads();
    if (tid < 64){
        float* row = satt + tid*16;
        float mx = row[0];
        #pragma unroll
        for (int e=1;e<16;e++) mx = fmaxf(mx, row[e]);
        float s = 0.f;
        #pragma unroll
        for (int e=0;e<16;e++){ float v = expf(row[e]-mx); row[e]=v; s+=v; }
        float inv = 1.f/s;
        #pragma unroll
        for (int e=0;e<16;e++) row[e] *= inv;
    }
    __syncthreads();
    for (int p = tid; p < 2048; p += 512){
        int e = p>>7, c = p&127, h = c>>5;
        float acc = 0.f;
        #pragma unroll
        for (int e2=0;e2<16;e2++) acc += satt[(h*16+e)*16 + e2] * s3[e2*132 + c];
        s1[e*132 + c] = acc;
    }
    __syncthreads();
    gemmF<128,128,0>(mha_w_out, mha_b_out, s1,132, s2,132, sw);
    ln16_128(s0, s2, 132, tnorm_g, tnorm_b, s3, 132);
    gemmF<128,256,1>(ffn_w1, ffn_b1, s3,132, sh,264, sw);
    gemmF<256,128,0>(ffn_w2, ffn_b2, sh,264, s1,132, sw);
    ln16_128(s3, s1, 132, tnorm_g, tnorm_b, s2, 132);
    ln16_128(s2, (const float*)0, 132, nh_g, nh_b, s3, 132);
    gemmF<128,128,1>(hp_w, hp_b, s3,132, s0,132, sw);               // H -> s0
    gemmF<128,128,0>(kv_w,           kv_b,     s0,132, s1,132, sw); // K -> s1
    gemmF<128,128,0>(kv_w + 128*128, kv_b+128, s0,132, s2,132, sw); // V -> s2

    for (int i = tid; i < 2048; i += 512){
        int e = i>>7, c = i&127, o = b*2048 + i;
        g_hyperF[o] = s0[e*132+c];
        g_K[o]      = s1[e*132+c];
        g_V[o]      = s2[e*132+c];
    }
}

// ============ kernel 3b: parallel precomputes (grid 33) ============
// blocks 0..31: b = blk>>2, task = blk&3. block 32: u,t + nproj weight split.
__global__ void __launch_bounds__(512)
k_prep(const float* __restrict__ q_w, const float* __restrict__ q_b,
       const float* __restrict__ gate_w, const float* __restrict__ gate_b,
       const float* __restrict__ nf_g, const float* __restrict__ nf_b,
       const float* __restrict__ nproj_w)
{
    extern __shared__ float sm[];
    float* s_w = sm;            // 128*132
    float* s_a = s_w + 16896;   // 16*132
    float* s_b = s_a + 2112;    // 16*132
    int tid = threadIdx.x;

    if (blockIdx.x == 32){
        if (tid < 128){
            int j = tid;
            float t = gate_b[j], u = 0.f;
            for (int c = 0; c < 256; c++){
                float w = gate_w[j*256 + c];
                t += nf_b[c]*w;
                u += nf_g[c]*w;
            }
            g_t[j] = t; g_u[j] = u;
        }
        // bf16 split pack of nproj_w (pairs along k)
        const float2* W2 = (const float2*)nproj_w;
        for (int i = tid; i < 8192; i += 512){
            unsigned int hi, lo;
            bf16_split2(W2[i], hi, lo);
            g_whp[i] = hi; g_wlp[i] = lo;
        }
        return;
    }

    int b = blockIdx.x >> 2, task = blockIdx.x & 3;

    if (task == 0){
        // Kp[e][k] = scl * sum_c K[e][c]*q_w[c][k];  kb[e] = scl * q_b . K[e]
        const float4* W4 = (const float4*)q_w;
        for (int i = tid; i < 4096; i += 512){
            int r = i >> 5, c4 = i & 31;
            ((float4*)(s_w + r*132))[c4] = W4[i];
        }
        for (int i = tid; i < 512; i += 512){}
        for (int i4 = tid; i4 < 512; i4 += 512){
            int e = i4 >> 5, c4 = i4 & 31;
            ((float4*)(s_a + e*132))[c4] = ((const float4*)(g_K + b*2048))[i4];
        }
        __syncthreads();
        const float scl = 0.08838834764831845f;
        for (int o = tid; o < 2048; o += 512){
            int e = o>>7, k = o&127;
            float acc = 0.f;
            for (int c = 0; c < 128; c++) acc += s_a[e*132+c]*s_w[c*132+k];
            g_Kp[b*2048 + o] = acc * scl;
        }
        if (tid < 16){
            float acc = 0.f;
            for (int c = 0; c < 128; c++) acc += q_b[c]*s_a[tid*132+c];
            g_kb[b*16 + tid] = acc * scl;
        }
    } else if (task == 1 || task == 2){
        // Hw[e][j] = sum_c H[e][c]*gw[j][off+c]*nf_g[off+c]  (task1: H/off0, task2: V/off128)
        int off = (task == 2) ? 128 : 0;
        const float* src = (task == 2) ? (g_V + b*2048) : (g_hyperF + b*2048);
        for (int i = tid; i < 16384; i += 512){
            int j = i >> 7, c = i & 127;
            s_w[j*132 + c] = gate_w[j*256 + off + c] * nf_g[off + c];
        }
        for (int i4 = tid; i4 < 512; i4 += 512){
            int e = i4 >> 5, c4 = i4 & 31;
            ((float4*)(s_a + e*132))[c4] = ((const float4*)src)[i4];
        }
        __syncthreads();
        float* dst = (task == 2) ? (g_Vw + b*2048) : (g_Hw + b*2048);
        for (int p = tid; p < 2048; p += 512){
            int e = p >> 7, j = p & 127;
            const float4* ar = (const float4*)(s_a + e*132);
            const float4* wr = (const float4*)(s_w + j*132);
            float acc = 0.f;
            #pragma unroll 8
            for (int kk = 0; kk < 32; kk++){
                float4 a = ar[kk], w = wr[kk];
                acc += a.x*w.x + a.y*w.y + a.z*w.z + a.w*w.w;
            }
            dst[p] = acc;
        }
    } else {
        // Gram matrices + row sums
        for (int i4 = tid; i4 < 1024; i4 += 512){
            int half = i4 >> 9, q = i4 & 511;
            int e = q >> 5, c4 = q & 31;
            float* dst = half ? s_b : s_a;
            const float4* src = half ? (const float4*)(g_V + b*2048)
                                     : (const float4*)(g_hyperF + b*2048);
            ((float4*)(dst + e*132))[c4] = src[q];
        }
        __syncthreads();
        if (tid < 512){
            const float* A = (tid < 256) ? s_a : s_b;
            int qq = tid & 255;
            int e = qq >> 4, f = qq & 15;
            const float4* r1 = (const float4*)(A + e*132);
            const float4* r2 = (const float4*)(A + f*132);
            float acc = 0.f;
            #pragma unroll 8
            for (int kk = 0; kk < 32; kk++){
                float4 a = r1[kk], c = r2[kk];
                acc += a.x*c.x + a.y*c.y + a.z*c.z + a.w*c.w;
            }
            if (tid < 256) g_GH[b*256+qq] = acc; else g_GV[b*256+qq] = acc;
        }
        if (tid < 32){
            int e = tid & 15;
            const float* A = (tid < 16) ? s_a : s_b;
            float s = 0.f;
            for (int c = 0; c < 128; c++) s += A[e*132+c];
            if (tid < 16) g_hs[b*16+e] = s; else g_vs[b*16+e] = s;
        }
    }
}

// ============ kernel 4: FUSED per-node pipeline ============
// grid 576 (8*72), block 512, 128 nodes/block
__global__ void __launch_bounds__(512)
k_node(const float* __restrict__ sc,
       const float* __restrict__ gl_g, const float* __restrict__ gl_b,
       const float* __restrict__ nproj_b,
       float* __restrict__ out)
{
    extern __shared__ float sm[];
    float* s_node = sm;              // 16896 (128*132)
    unsigned int* s_wh = (unsigned int*)(s_node + 16896);  // 128*68
    unsigned int* s_wl = s_wh + 8704;                      // 128*68
    float* s_Kp   = (float*)(s_wl + 8704);  // 2112
    float* s_H    = s_Kp   + 2112;
    float* s_V    = s_H    + 2112;
    float* s_Hw   = s_V    + 2112;
    float* s_Vw   = s_Hw   + 2112;
    float* s_att  = s_Vw   + 2112;   // 2048
    float* s_sc   = s_att  + 2048;   // 2048
    float* s_GH   = s_sc   + 2048;   // 256
    float* s_GV   = s_GH   + 256;
    float* s_u    = s_GV   + 256;    // 128
    float* s_t    = s_u    + 128;
    float* s_m    = s_t    + 128;    // 128 (LN256 then gate-LN)
    float* s_rs   = s_m    + 128;
    float* s_sp   = s_rs   + 128;    // 512 gate-LN sum partials
    float* s_sq   = s_sp   + 512;    // 512
    float* s_hs   = s_sq   + 512;    // 16
    float* s_vs   = s_hs   + 16;
    float* s_kb   = s_vs   + 16;

    int b  = blockIdx.x / 72;
    int n0 = (blockIdx.x % 72) * 128;
    int tid = threadIdx.x;

    // ---- stage everything (incl. split weights) ----
    for (int i4 = tid; i4 < 4096; i4 += 512){
        int n = i4 >> 5, c4 = i4 & 31;
        ((float4*)(s_node + n*132))[c4] =
            ((const float4*)(g_node + (size_t)(b*NN + n0 + n)*CC))[c4];
    }
    for (int i = tid; i < 8192; i += 512){
        int j = i >> 6, kk = i & 63;
        s_wh[j*68 + kk] = g_whp[i];
        s_wl[j*68 + kk] = g_wlp[i];
    }
    {
        int i4 = tid;
        if (i4 < 512){
            int e = i4 >> 5, c4 = i4 & 31;
            ((float4*)(s_Kp + e*132))[c4] = ((const float4*)(g_Kp    + b*2048))[i4];
            ((float4*)(s_H  + e*132))[c4] = ((const float4*)(g_hyperF+ b*2048))[i4];
            ((float4*)(s_V  + e*132))[c4] = ((const float4*)(g_V     + b*2048))[i4];
            ((float4*)(s_Hw + e*132))[c4] = ((const float4*)(g_Hw    + b*2048))[i4];
            ((float4*)(s_Vw + e*132))[c4] = ((const float4*)(g_Vw    + b*2048))[i4];
        }
        if (i4 < 512) ((float4*)s_sc)[i4] = ((const float4*)(sc + (size_t)(b*NN + n0)*16))[i4];
        if (i4 < 64){
            ((float4*)s_GH)[i4] = ((const float4*)(g_GH + b*256))[i4];
            ((float4*)s_GV)[i4] = ((const float4*)(g_GV + b*256))[i4];
        }
        if (i4 < 32){
            ((float4*)s_u)[i4] = ((const float4*)g_u)[i4];
            ((float4*)s_t)[i4] = ((const float4*)g_t)[i4];
        }
        if (i4 < 16){ s_hs[i4]=g_hs[b*16+i4]; s_vs[i4]=g_vs[b*16+i4]; s_kb[i4]=g_kb[b*16+i4]; }
    }
    __syncthreads();

    // ---- logits ----
    {
        int n = tid >> 2, q = tid & 3;
        const float4* nr = (const float4*)(s_node + n*132);
        float acc[4] = {0.f,0.f,0.f,0.f};
        const float4* kp0 = (const float4*)(s_Kp + (q*4+0)*132);
        const float4* kp1 = (const float4*)(s_Kp + (q*4+1)*132);
        const float4* kp2 = (const float4*)(s_Kp + (q*4+2)*132);
        const float4* kp3 = (const float4*)(s_Kp + (q*4+3)*132);
        #pragma unroll 8
        for (int kk = 0; kk < 32; kk++){
            float4 a = nr[kk];
            float4 k0 = kp0[kk], k1 = kp1[kk], k2 = kp2[kk], k3 = kp3[kk];
            acc[0] += a.x*k0.x + a.y*k0.y + a.z*k0.z + a.w*k0.w;
            acc[1] += a.x*k1.x + a.y*k1.y + a.z*k1.z + a.w*k1.w;
            acc[2] += a.x*k2.x + a.y*k2.y + a.z*k2.z + a.w*k2.w;
            acc[3] += a.x*k3.x + a.y*k3.y + a.z*k3.z + a.w*k3.w;
        }
        #pragma unroll
        for (int i=0;i<4;i++) s_att[n*16 + q*4 + i] = acc[i] + s_kb[q*4+i];
    }
    __syncthreads();

    // ---- softmax + LN256 stats ----
    if (tid < 128){
        int n = tid;
        float scv[16], atv[16];
        float* row = s_att + n*16;
        float mx = row[0];
        #pragma unroll
        for (int e=1;e<16;e++) mx = fmaxf(mx, row[e]);
        float s = 0.f;
        #pragma unroll
        for (int e=0;e<16;e++){ float v = expf(row[e]-mx); atv[e]=v; s+=v; }
        float inv = 1.f/s;
        #pragma unroll
        for (int e=0;e<16;e++){ atv[e] *= inv; row[e] = atv[e]; scv[e] = s_sc[n*16+e]; }
        float mean = 0.f;
        #pragma unroll
        for (int e=0;e<16;e++) mean += scv[e]*s_hs[e] + atv[e]*s_vs[e];
        mean *= (1.f/256.f);
        float ssq = 0.f;
        #pragma unroll
        for (int e=0;e<16;e++){
            float t1 = 0.f, t2 = 0.f;
            #pragma unroll
            for (int f=0;f<16;f++){
                t1 += scv[f]*s_GH[e*16+f];
                t2 += atv[f]*s_GV[e*16+f];
            }
            ssq += scv[e]*t1 + atv[e]*t2;
        }
        float var = ssq*(1.f/256.f) - mean*mean;
        s_m[n] = mean;
        s_rs[n] = rsqrtf(var + 1e-5f);
    }
    __syncthreads();

    // ---- gate rank-16 in registers + LN stat partials ----
    float gp[4][8];
    {
        int j = tid & 127, g = tid >> 7, sub = (tid >> 5) & 3;
        float uj = s_u[j], tj = s_t[j];
        #pragma unroll
        for (int blk = 0; blk < 4; blk++){
            int nb = g*32 + blk*8;
            float acc[8] = {0,0,0,0,0,0,0,0};
            #pragma unroll
            for (int kk = 0; kk < 4; kk++){
                float b0 = s_Hw[(kk*4+0)*132 + j];
                float b1 = s_Hw[(kk*4+1)*132 + j];
                float b2 = s_Hw[(kk*4+2)*132 + j];
                float b3 = s_Hw[(kk*4+3)*132 + j];
                #pragma unroll
                for (int i=0;i<8;i++){
                    float4 a = ((const float4*)(s_sc + (nb+i)*16))[kk];
                    acc[i] += a.x*b0 + a.y*b1 + a.z*b2 + a.w*b3;
                }
            }
            #pragma unroll
            for (int kk = 0; kk < 4; kk++){
                float b0 = s_Vw[(kk*4+0)*132 + j];
                float b1 = s_Vw[(kk*4+1)*132 + j];
                float b2 = s_Vw[(kk*4+2)*132 + j];
                float b3 = s_Vw[(kk*4+3)*132 + j];
                #pragma unroll
                for (int i=0;i<8;i++){
                    float4 a = ((const float4*)(s_att + (nb+i)*16))[kk];
                    acc[i] += a.x*b0 + a.y*b1 + a.z*b2 + a.w*b3;
                }
            }
            #pragma unroll
            for (int i=0;i<8;i++){
                int n = nb + i;
                float v = s_rs[n]*(acc[i] - s_m[n]*uj) + tj;
                gp[blk][i] = v;
                float s1 = v, s2 = v*v;
                for (int o=16;o;o>>=1){
                    s1 += __shfl_xor_sync(0xffffffffu, s1, o);
                    s2 += __shfl_xor_sync(0xffffffffu, s2, o);
                }
                if ((tid & 31) == 0){
                    s_sp[n*4 + sub] = s1;
                    s_sq[n*4 + sub] = s2;
                }
            }
        }
    }
    __syncthreads();

    // ---- gate LN stats finalize (reuse s_m/s_rs) ----
    if (tid < 128){
        int n = tid;
        float s1 = s_sp[n*4] + s_sp[n*4+1] + s_sp[n*4+2] + s_sp[n*4+3];
        float s2 = s_sq[n*4] + s_sq[n*4+1] + s_sq[n*4+2] + s_sq[n*4+3];
        float m = s1*(1.f/128.f);
        float var = s2*(1.f/128.f) - m*m;
        s_m[n] = m;
        s_rs[n] = rsqrtf(var + 1e-5f);
    }
    __syncthreads();

    // ---- sigmoid (regs) + upd into s_node ----
    {
        int c = tid & 127, g = tid >> 7;
        float gj = gl_g[c], bj = gl_b[c];
        float hcol[16], vcol[16];
        #pragma unroll
        for (int e=0;e<16;e++){ hcol[e] = s_H[e*132+c]; vcol[e] = s_V[e*132+c]; }
        #pragma unroll
        for (int blk = 0; blk < 4; blk++){
            #pragma unroll
            for (int i=0;i<8;i++){
                int n = g*32 + blk*8 + i;
                float gt = 1.f/(1.f + expf(-((gp[blk][i]-s_m[n])*s_rs[n]*gj + bj)));
                float intra = 0.f, cross = 0.f;
                #pragma unroll
                for (int kk=0; kk<4; kk++){
                    float4 a = ((const float4*)(s_sc  + n*16))[kk];
                    float4 t = ((const float4*)(s_att + n*16))[kk];
                    intra += a.x*hcol[kk*4] + a.y*hcol[kk*4+1] + a.z*hcol[kk*4+2] + a.w*hcol[kk*4+3];
                    cross += t.x*vcol[kk*4] + t.y*vcol[kk*4+1] + t.z*vcol[kk*4+2] + t.w*vcol[kk*4+3];
                }
                s_node[n*132+c] = s_node[n*132+c] + gt*intra + (1.f-gt)*cross;
            }
        }
    }
    __syncthreads();

    // ---- nproj via bf16 tensor cores (3x split) ----
    {
        int lane = tid & 31, w = tid >> 5;
        int nb  = (w & 7) * 16;
        int jb0 = (w >> 3) * 64;
        int g = lane >> 2, t = lane & 3;
        const float* An0 = s_node + (nb + g)*132;
        const float* An1 = s_node + (nb + g + 8)*132;

        float acc[8][4];
        #pragma unroll
        for (int jt=0;jt<8;jt++){
            acc[jt][0]=0.f; acc[jt][1]=0.f; acc[jt][2]=0.f; acc[jt][3]=0.f;
        }

        #pragma unroll 2
        for (int kc = 0; kc < 8; kc++){
            int kb = kc*16;
            float2 p0 = *(const float2*)(An0 + kb + 2*t);
            float2 p1 = *(const float2*)(An1 + kb + 2*t);
            float2 p2 = *(const float2*)(An0 + kb + 2*t + 8);
            float2 p3 = *(const float2*)(An1 + kb + 2*t + 8);
            unsigned int aH[4], aL[4];
            bf16_split2(p0, aH[0], aL[0]);
            bf16_split2(p1, aH[1], aL[1]);
            bf16_split2(p2, aH[2], aL[2]);
            bf16_split2(p3, aH[3], aL[3]);
            #pragma unroll
            for (int jt = 0; jt < 8; jt++){
                int j = jb0 + jt*8 + g;
                unsigned int b0h = s_wh[j*68 + kc*8 + t];
                unsigned int b1h = s_wh[j*68 + kc*8 + t + 4];
                unsigned int b0l = s_wl[j*68 + kc*8 + t];
                unsigned int b1l = s_wl[j*68 + kc*8 + t + 4];
                mma_bf16(acc[jt], aH, b0h, b1h);
                mma_bf16(acc[jt], aH, b0l, b1l);
                mma_bf16(acc[jt], aL, b0h, b1h);
            }
        }

        int nlo = n0 + nb + g;
        int nhi = nlo + 8;
        #pragma unroll
        for (int jt = 0; jt < 8; jt++){
            int j0 = jb0 + jt*8 + 2*t;
            float bias0 = nproj_b[j0], bias1 = nproj_b[j0+1];
            out[(size_t)(b*CC + j0    )*NN + nlo] = gelu_exact(acc[jt][0] + bias0);
            out[(size_t)(b*CC + j0 + 1)*NN + nlo] = gelu_exact(acc[jt][1] + bias1);
            out[(size_t)(b*CC + j0    )*NN + nhi] = gelu_exact(acc[jt][2] + bias0);
            out[(size_t)(b*CC + j0 + 1)*NN + nhi] = gelu_exact(acc[jt][3] + bias1);
        }
    }
}

// ---------------- launch ----------------
extern "C" void kernel_launch(void* const* d_in, const int* in_sizes, int n_in,
                              void* d_out, int out_size)
{
    const float* fm        = (const float*)d_in[0];
    const float* sc        = (const float*)d_in[1];
    const float* np_g      = (const float*)d_in[2];
    const float* np_b      = (const float*)d_in[3];
    const float* mha_w_in  = (const float*)d_in[4];
    const float* mha_b_in  = (const float*)d_in[5];
    const float* mha_w_out = (const float*)d_in[6];
    const float* mha_b_out = (const float*)d_in[7];
    const float* ffn_w1    = (const float*)d_in[8];
    const float* ffn_b1    = (const float*)d_in[9];
    const float* ffn_w2    = (const float*)d_in[10];
    const float* ffn_b2    = (const float*)d_in[11];
    const float* tnorm_g   = (const float*)d_in[12];
    const float* tnorm_b   = (const float*)d_in[13];
    const float* nh_g      = (const float*)d_in[14];
    const float* nh_b      = (const float*)d_in[15];
    const float* hp_w      = (const float*)d_in[16];
    const float* hp_b      = (const float*)d_in[17];
    const float* q_w       = (const float*)d_in[18];
    const float* q_b       = (const float*)d_in[19];
    const float* kv_w      = (const float*)d_in[20];
    const float* kv_b      = (const float*)d_in[21];
    const float* nf_g      = (const float*)d_in[22];
    const float* nf_b      = (const float*)d_in[23];
    const float* gate_w    = (const float*)d_in[24];
    const float* gate_b    = (const float*)d_in[25];
    const float* gl_g      = (const float*)d_in[26];
    const float* gl_b      = (const float*)d_in[27];
    const float* nproj_w   = (const float*)d_in[28];
    const float* nproj_b   = (const float*)d_in[29];

    const int smem_nodeln = (16896 + 2048 + 8192 + 256) * 4;       // 109568
    const int smem_hyper  = (2112*4 + 4224 + 1024 + 33792) * 4;    // 189952
    const int smem_prep   = (16896 + 2112*2) * 4;                  // 84480
    const int smem_node   = (16896 + 8704*2 + 2112*5 + 2048*2
                             + 256*2 + 128*4 + 1024 + 48) * 4;     // 204224

    cudaFuncSetAttribute(k_node_ln, cudaFuncAttributeMaxDynamicSharedMemorySize, smem_nodeln);
    cudaFuncSetAttribute(k_hyper,   cudaFuncAttributeMaxDynamicSharedMemorySize, smem_hyper);
    cudaFuncSetAttribute(k_prep,    cudaFuncAttributeMaxDynamicSharedMemorySize, smem_prep);
    cudaFuncSetAttribute(k_node,    cudaFuncAttributeMaxDynamicSharedMemorySize, smem_node);

    k_node_ln<<<576, 512, smem_nodeln>>>(fm, np_g, np_b, sc);
    k_reduce<<<128, 128>>>();
    k_hyper<<<8, 512, smem_hyper>>>(mha_w_in, mha_b_in, mha_w_out, mha_b_out,
                                    ffn_w1, ffn_b1, ffn_w2, ffn_b2,
                                    tnorm_g, tnorm_b, nh_g, nh_b,
                                    hp_w, hp_b, kv_w, kv_b);
    k_prep<<<33, 512, smem_prep>>>(q_w, q_b, gate_w, gate_b, nf_g, nf_b, nproj_w);
    k_node<<<576, 512, smem_node>>>(sc, gl_g, gl_b, nproj_b, (float*)d_out);
}